// round 12
// baseline (speedup 1.0000x reference)
#include <cuda_runtime.h>
#include <cuda_fp16.h>
#include <cstdint>

#define SEQ 384
#define CIN 512
#define HW  64
#define NH  8
#define HD  64
#define K9  (CIN * 9)        // 4608
#define BP  512              // NH * HW batch-pairs
#define NROWS (SEQ * HW)     // 24576 GEMM rows
#define SS2 (SEQ * SEQ)      // 147456
#define WROWS (SEQ * 16)     // 6144 Winograd GEMM rows
#define NCO 2560

// Scratch (device globals; no runtime allocation)
__device__ uint32_t g_feats_hl[(size_t)4 * BP * SEQ * HD];  // [e][bp][n][dd] packed(hi,lo)
__device__ uint32_t g_vT[(size_t)BP * HD * SEQ];            // [bp][dd][n]   packed(hi,lo)
__device__ uint32_t g_attn[(size_t)BP * SS2];               // blended attn, packed(hi,lo)
__device__ uint32_t g_c2_hl[(size_t)SEQ * CIN * HW];        // conv2 input, packed(hi,lo)
__device__ __half   g_Ah[(size_t)NROWS * K9];               // im2col hi plane (conv_out)
__device__ __half   g_Al[(size_t)NROWS * K9];               // im2col lo plane
__device__ __half   g_wh_out[(size_t)512 * K9];
__device__ __half   g_wl_out[(size_t)512 * K9];
// Winograd buffers (conv_in)
__device__ __half   g_Vh[(size_t)16 * WROWS * CIN];         // transformed input hi
__device__ __half   g_Vl[(size_t)16 * WROWS * CIN];
__device__ __half   g_Uh[(size_t)16 * NCO * CIN];           // transformed weights hi
__device__ __half   g_Ul[(size_t)16 * NCO * CIN];
__device__ float    g_M[(size_t)16 * WROWS * NCO];          // transform-domain products (1GB)

// ---------------------------------------------------------------------------
// helpers
// ---------------------------------------------------------------------------
__device__ __forceinline__ uint32_t split_h2(float x)
{
    __half hi = __float2half_rn(x);
    __half lo = __float2half_rn(x - __half2float(hi));
    return (uint32_t)__half_as_ushort(hi) | ((uint32_t)__half_as_ushort(lo) << 16);
}
__device__ __forceinline__ float unsplit_h2(uint32_t p)
{
    return __half2float(__ushort_as_half((unsigned short)(p & 0xFFFF)))
         + __half2float(__ushort_as_half((unsigned short)(p >> 16)));
}

__device__ __forceinline__ void mma_f16(float c[4], const uint32_t a[4],
                                        uint32_t b0, uint32_t b1)
{
    asm volatile(
        "mma.sync.aligned.m16n8k16.row.col.f32.f16.f16.f32 "
        "{%0,%1,%2,%3}, {%4,%5,%6,%7}, {%8,%9}, {%0,%1,%2,%3};"
        : "+f"(c[0]), "+f"(c[1]), "+f"(c[2]), "+f"(c[3])
        : "r"(a[0]), "r"(a[1]), "r"(a[2]), "r"(a[3]), "r"(b0), "r"(b1));
}
__device__ __forceinline__ void ldsm4(uint32_t& r0, uint32_t& r1, uint32_t& r2,
                                      uint32_t& r3, uint32_t addr)
{
    asm volatile("ldmatrix.sync.aligned.m8n8.x4.shared.b16 {%0,%1,%2,%3}, [%4];"
                 : "=r"(r0), "=r"(r1), "=r"(r2), "=r"(r3) : "r"(addr));
}
__device__ __forceinline__ void cpa16(uint32_t dst, const void* src)
{
    asm volatile("cp.async.cg.shared.global [%0], [%1], 16;" :: "r"(dst), "l"(src));
}

// ---------------------------------------------------------------------------
// conv_out weight split + permute to k' = r*512 + ci order
// ---------------------------------------------------------------------------
__global__ void split_w_kernel(const float* __restrict__ w,
                               __half* __restrict__ wh, __half* __restrict__ wl, int n)
{
    int i = blockIdx.x * 256 + threadIdx.x;
    if (i >= n) return;
    int co = i / K9;
    int kn = i - co * K9;
    int r = kn >> 9, ci = kn & 511;
    float x = w[(size_t)co * K9 + ci * 9 + r];
    __half hi = __float2half_rn(x);
    wh[i] = hi;
    wl[i] = __float2half_rn(x - __half2float(hi));
}

// ---------------------------------------------------------------------------
// Winograd weight transform: U = G g G^T per (co, ci), split hi/lo.
// Layout: g_U*[xi*4+nu][co*512 + ci].
// ---------------------------------------------------------------------------
__global__ void wino_w_kernel(const float* __restrict__ w)
{
    int i = blockIdx.x * 256 + threadIdx.x;
    if (i >= NCO * CIN) return;
    int co = i >> 9, ci = i & 511;
    const float* g = w + (size_t)co * K9 + ci * 9;
    float g0 = g[0], g1 = g[1], g2 = g[2];
    float g3 = g[3], g4 = g[4], g5 = g[5];
    float g6 = g[6], g7 = g[7], g8 = g[8];
    float T[4][3] = {
        {g0, g1, g2},
        {0.5f * (g0 + g3 + g6), 0.5f * (g1 + g4 + g7), 0.5f * (g2 + g5 + g8)},
        {0.5f * (g0 - g3 + g6), 0.5f * (g1 - g4 + g7), 0.5f * (g2 - g5 + g8)},
        {g6, g7, g8}};
    #pragma unroll
    for (int r = 0; r < 4; r++) {
        float Us[4];
        Us[0] = T[r][0];
        Us[1] = 0.5f * (T[r][0] + T[r][1] + T[r][2]);
        Us[2] = 0.5f * (T[r][0] - T[r][1] + T[r][2]);
        Us[3] = T[r][2];
        #pragma unroll
        for (int c2 = 0; c2 < 4; c2++) {
            size_t o = (size_t)(r * 4 + c2) * (NCO * CIN) + (size_t)co * CIN + ci;
            __half hi = __float2half_rn(Us[c2]);
            g_Uh[o] = hi;
            g_Ul[o] = __float2half_rn(Us[c2] - __half2float(hi));
        }
    }
}

// ---------------------------------------------------------------------------
// Winograd input transform: V = B^T d B per (img, ci, tile), split hi/lo.
// Layout: g_V*[xi*4+nu][(img*16+t)*512 + ci]. Grid (384, 8 ci-chunks), 256 thr.
// ---------------------------------------------------------------------------
__global__ __launch_bounds__(256) void wino_in_kernel(const float* __restrict__ inp)
{
    __shared__ float ts[64][65];   // [sp][ci_local]
    const int img = blockIdx.x;
    const int ci0 = blockIdx.y * 64;
    const int tid = threadIdx.x;

    {
        int sp4 = (tid & 15) * 4;
        int ciL = tid >> 4;
        #pragma unroll
        for (int pass = 0; pass < 4; pass++) {
            int ci = pass * 16 + ciL;
            float4 v = *(const float4*)(inp + ((size_t)img * CIN + ci0 + ci) * 64 + sp4);
            ts[sp4 + 0][ci] = v.x;
            ts[sp4 + 1][ci] = v.y;
            ts[sp4 + 2][ci] = v.z;
            ts[sp4 + 3][ci] = v.w;
        }
    }
    __syncthreads();

    #pragma unroll
    for (int pass = 0; pass < 4; pass++) {
        int item = pass * 256 + tid;
        int tt = item >> 6;            // 0..15
        int ci = item & 63;
        int ty = tt >> 2, tx = tt & 3;
        float d[4][4];
        #pragma unroll
        for (int r = 0; r < 4; r++) {
            int y = 2 * ty - 1 + r;
            #pragma unroll
            for (int s = 0; s < 4; s++) {
                int x = 2 * tx - 1 + s;
                d[r][s] = ((unsigned)y < 8u && (unsigned)x < 8u) ? ts[y * 8 + x][ci] : 0.f;
            }
        }
        float tm[4][4];
        #pragma unroll
        for (int s = 0; s < 4; s++) {
            tm[0][s] = d[0][s] - d[2][s];
            tm[1][s] = d[1][s] + d[2][s];
            tm[2][s] = d[2][s] - d[1][s];
            tm[3][s] = d[1][s] - d[3][s];
        }
        size_t rowbase = ((size_t)img * 16 + tt) * CIN + ci0 + ci;
        #pragma unroll
        for (int r = 0; r < 4; r++) {
            float V0 = tm[r][0] - tm[r][2];
            float V1 = tm[r][1] + tm[r][2];
            float V2 = tm[r][2] - tm[r][1];
            float V3 = tm[r][1] - tm[r][3];
            float Vs[4] = {V0, V1, V2, V3};
            #pragma unroll
            for (int c2 = 0; c2 < 4; c2++) {
                size_t o = (size_t)(r * 4 + c2) * ((size_t)WROWS * CIN) + rowbase;
                __half hi = __float2half_rn(Vs[c2]);
                g_Vh[o] = hi;
                g_Vl[o] = __float2half_rn(Vs[c2] - __half2float(hi));
            }
        }
    }
}

// ---------------------------------------------------------------------------
// Winograd GEMM: M[z][row][co] += V[z][row][ci] * U[z][co][ci], K=512.
// Identical mainloop to the proven R11 conv kernel (128x128 tile, 2-stage
// cp.async, term-major MMA order). Grid (20 co-tiles, 48 row-tiles, 16 z).
// ---------------------------------------------------------------------------
#define LDK2 20
#define STG_BYTES (4 * 128 * LDK2 * 4)
#define SMEM_BYTES (2 * STG_BYTES)

__device__ __forceinline__ void wino_fill(uint32_t base, size_t va, size_t ua,
                                          int row0, int co0, int k0, int tid)
{
    #pragma unroll
    for (int h = 0; h < 2; h++) {
        int c = h * 256 + tid;
        int row = c >> 2, q = c & 3;
        uint32_t doff = (uint32_t)((row * LDK2 + q * 4) * 4);
        size_t aoff = va + (size_t)(row0 + row) * CIN + k0 + q * 8;
        size_t boff = ua + (size_t)(co0 + row) * CIN + k0 + q * 8;
        cpa16(base + doff,         g_Vh + aoff);
        cpa16(base + 10240 + doff, g_Vl + aoff);
        cpa16(base + 20480 + doff, g_Uh + boff);
        cpa16(base + 30720 + doff, g_Ul + boff);
    }
    asm volatile("cp.async.commit_group;" ::: "memory");
}

__global__ void __launch_bounds__(256, 2)
wino_gemm_kernel()
{
    extern __shared__ uint32_t sm[];
    const uint32_t smb = (uint32_t)__cvta_generic_to_shared(sm);

    const int row0 = blockIdx.y * 128;
    const int co0  = blockIdx.x * 128;
    const size_t va = (size_t)blockIdx.z * ((size_t)WROWS * CIN);
    const size_t ua = (size_t)blockIdx.z * ((size_t)NCO * CIN);
    const int tid  = threadIdx.x;
    const int lane = tid & 31, wid = tid >> 5;
    const int rbase = (wid >> 1) * 32;
    const int cbase = (wid & 1) * 64;
    const int lg = lane >> 2, lt = lane & 3;

    const int aRow = lane & 15, aCol = (lane >> 4) * 4;
    const int bRow = ((lane >> 4) & 1) * 8 + (lane & 7);
    const int bCol = ((lane >> 3) & 1) * 4;

    float acc[2][8][4] = {};

    wino_fill(smb, va, ua, row0, co0, 0, tid);

    const int NITER = CIN / 32;   // 16
    for (int it = 0; it < NITER; it++) {
        const int s = it & 1;
        asm volatile("cp.async.wait_group 0;" ::: "memory");
        __syncthreads();
        if (it + 1 < NITER)
            wino_fill(smb + (1 - s) * STG_BYTES, va, ua, row0, co0, (it + 1) * 32, tid);

        const uint32_t base = smb + s * STG_BYTES;
        #pragma unroll
        for (int k16 = 0; k16 < 2; k16++) {
            const uint32_t ko = k16 * 8;
            uint32_t ah[2][4], al[2][4];
            #pragma unroll
            for (int mt = 0; mt < 2; mt++) {
                uint32_t aw = base + ((rbase + mt * 16 + aRow) * LDK2 + aCol + ko) * 4;
                ldsm4(ah[mt][0], ah[mt][1], ah[mt][2], ah[mt][3], aw);
                ldsm4(al[mt][0], al[mt][1], al[mt][2], al[mt][3], aw + 10240);
            }
            #pragma unroll
            for (int pr = 0; pr < 4; pr++) {
                uint32_t bw = base + 20480 +
                              ((cbase + pr * 16 + bRow) * LDK2 + bCol + ko) * 4;
                uint32_t bh0, bh1, bh2, bh3, bl0, bl1, bl2, bl3;
                ldsm4(bh0, bh1, bh2, bh3, bw);
                ldsm4(bl0, bl1, bl2, bl3, bw + 10240);
                mma_f16(acc[0][2 * pr],     ah[0], bh0, bh1);
                mma_f16(acc[1][2 * pr],     ah[1], bh0, bh1);
                mma_f16(acc[0][2 * pr + 1], ah[0], bh2, bh3);
                mma_f16(acc[1][2 * pr + 1], ah[1], bh2, bh3);
                mma_f16(acc[0][2 * pr],     ah[0], bl0, bl1);
                mma_f16(acc[1][2 * pr],     ah[1], bl0, bl1);
                mma_f16(acc[0][2 * pr + 1], ah[0], bl2, bl3);
                mma_f16(acc[1][2 * pr + 1], ah[1], bl2, bl3);
                mma_f16(acc[0][2 * pr],     al[0], bh0, bh1);
                mma_f16(acc[1][2 * pr],     al[1], bh0, bh1);
                mma_f16(acc[0][2 * pr + 1], al[0], bh2, bh3);
                mma_f16(acc[1][2 * pr + 1], al[1], bh2, bh3);
            }
        }
    }

    float* Mz = g_M + (size_t)blockIdx.z * ((size_t)WROWS * NCO);
    #pragma unroll
    for (int mt = 0; mt < 2; mt++) {
        #pragma unroll
        for (int nt = 0; nt < 8; nt++) {
            #pragma unroll
            for (int cp = 0; cp < 4; cp++) {
                int row = row0 + rbase + mt * 16 + lg + ((cp >= 2) ? 8 : 0);
                int col = co0 + cbase + nt * 8 + lt * 2 + (cp & 1);
                Mz[(size_t)row * NCO + col] = acc[mt][nt][cp];
            }
        }
    }
}

// ---------------------------------------------------------------------------
// Winograd output transform: Y = A^T M A + bias, then split/scatter to the
// attention layouts (g_feats_hl / g_vT). Grid (384 img, 40 co-chunks of 64).
// ---------------------------------------------------------------------------
#define WO_SMEM (16 * 16 * 64 * 4)   // 65536

__global__ __launch_bounds__(256) void wino_out_kernel(const float* __restrict__ bias)
{
    extern __shared__ float ms[];   // [xn][t][64 co]
    const int img = blockIdx.x;
    const int co0 = blockIdx.y * 64;
    const int tid = threadIdx.x;

    #pragma unroll
    for (int i = 0; i < 16; i++) {
        int lin = i * 256 + tid;       // float4 units, 4096 total
        int xn = lin >> 8;
        int rem = lin & 255;
        int tt = rem >> 4, co4 = (rem & 15) * 4;
        float4 v = *(const float4*)(g_M +
            ((size_t)xn * WROWS + img * 16 + tt) * NCO + co0 + co4);
        *(float4*)&ms[(xn * 16 + tt) * 64 + co4] = v;
    }
    __syncthreads();

    #pragma unroll
    for (int pass = 0; pass < 4; pass++) {
        int item = pass * 256 + tid;
        int tt = item >> 6, co = item & 63;
        int gco = co0 + co;
        float m[4][4];
        #pragma unroll
        for (int xi = 0; xi < 4; xi++)
            #pragma unroll
            for (int nu = 0; nu < 4; nu++)
                m[xi][nu] = ms[((xi * 4 + nu) * 16 + tt) * 64 + co];
        float t0[4], t1[4];
        #pragma unroll
        for (int nu = 0; nu < 4; nu++) {
            t0[nu] = m[0][nu] + m[1][nu] + m[2][nu];
            t1[nu] = m[1][nu] - m[2][nu] - m[3][nu];
        }
        float b = __ldg(&bias[gco]);
        float Ys[2][2];
        Ys[0][0] = t0[0] + t0[1] + t0[2] + b;
        Ys[0][1] = t0[1] - t0[2] - t0[3] + b;
        Ys[1][0] = t1[0] + t1[1] + t1[2] + b;
        Ys[1][1] = t1[1] - t1[2] - t1[3] + b;

        int ty = tt >> 2, tx = tt & 3;
        int e = gco >> 9, dd = (gco >> 3) & 63, hh = gco & 7;
        #pragma unroll
        for (int dy = 0; dy < 2; dy++)
            #pragma unroll
            for (int dx = 0; dx < 2; dx++) {
                int sp = (2 * ty + dy) * 8 + (2 * tx + dx);
                int bpi = hh * 64 + sp;
                uint32_t pv = split_h2(Ys[dy][dx]);
                if (e < 4)
                    g_feats_hl[(((size_t)e * BP + bpi) * SEQ + img) * HD + dd] = pv;
                else
                    g_vT[((size_t)bpi * HD + dd) * SEQ + img] = pv;
            }
    }
}

// ---------------------------------------------------------------------------
// im2col expansion (conv_out only): packed attn output -> hi/lo fp16 planes.
// ---------------------------------------------------------------------------
__global__ __launch_bounds__(256) void im2col_kernel()
{
    __shared__ ushort th[64][72];
    __shared__ ushort tl[64][72];
    const int n   = blockIdx.x;
    const int ci0 = blockIdx.y * 64;
    const int t   = threadIdx.x;

    {
        int sp4 = (t & 15) * 4;
        int ciL = t >> 4;
        #pragma unroll
        for (int pass = 0; pass < 4; pass++) {
            int ci = pass * 16 + ciL;
            uint4 w = *(const uint4*)(g_c2_hl + ((size_t)n * CIN + ci0 + ci) * 64 + sp4);
            uint32_t ws[4] = {w.x, w.y, w.z, w.w};
            #pragma unroll
            for (int j = 0; j < 4; j++) {
                th[sp4 + j][ci] = (ushort)(ws[j] & 0xFFFF);
                tl[sp4 + j][ci] = (ushort)(ws[j] >> 16);
            }
        }
    }
    __syncthreads();

    const int ciQ = t & 15;
    const int rg  = t >> 4;
    #pragma unroll
    for (int si = 0; si < 4; si++) {
        int sp = si * 16 + rg;
        int yy = sp >> 3, xx = sp & 7;
        size_t obase = (size_t)(n * 64 + sp) * K9 + ci0 + ciQ * 4;
        #pragma unroll
        for (int r = 0; r < 9; r++) {
            int y = yy + r / 3 - 1, x = xx + r % 3 - 1;
            uint2 vh = make_uint2(0, 0), vl = make_uint2(0, 0);
            if ((unsigned)y < 8u && (unsigned)x < 8u) {
                int spp = y * 8 + x;
                vh = *(const uint2*)&th[spp][ciQ * 4];
                vl = *(const uint2*)&tl[spp][ciQ * 4];
            }
            *(uint2*)&g_Ah[obase + (size_t)r * 512] = vh;
            *(uint2*)&g_Al[obase + (size_t)r * 512] = vl;
        }
    }
}

// ---------------------------------------------------------------------------
// Dense fp16x3 GEMM conv (R11 form) — conv_out only.
// ---------------------------------------------------------------------------
__device__ __forceinline__ void conv_fill(uint32_t base, int row0, int co0, int k0,
                                          int tid, const __half* gwh, const __half* gwl)
{
    #pragma unroll
    for (int h = 0; h < 2; h++) {
        int c = h * 256 + tid;
        int row = c >> 2, q = c & 3;
        uint32_t doff = (uint32_t)((row * LDK2 + q * 4) * 4);
        size_t aoff = (size_t)(row0 + row) * K9 + k0 + q * 8;
        size_t boff = (size_t)(co0 + row) * K9 + k0 + q * 8;
        cpa16(base + doff,         g_Ah + aoff);
        cpa16(base + 10240 + doff, g_Al + aoff);
        cpa16(base + 20480 + doff, gwh + boff);
        cpa16(base + 30720 + doff, gwl + boff);
    }
    asm volatile("cp.async.commit_group;" ::: "memory");
}

__global__ void __launch_bounds__(256, 2)
conv_f16_kernel(const __half* __restrict__ gwh,
                const __half* __restrict__ gwl,
                const float* __restrict__ bias,
                float* __restrict__ out)
{
    extern __shared__ uint32_t sm[];
    const uint32_t smb = (uint32_t)__cvta_generic_to_shared(sm);

    const int row0 = blockIdx.y * 128;
    const int co0  = blockIdx.x * 128;
    const int tid  = threadIdx.x;
    const int lane = tid & 31, wid = tid >> 5;
    const int rbase = (wid >> 1) * 32;
    const int cbase = (wid & 1) * 64;
    const int lg = lane >> 2, lt = lane & 3;

    const int aRow = lane & 15, aCol = (lane >> 4) * 4;
    const int bRow = ((lane >> 4) & 1) * 8 + (lane & 7);
    const int bCol = ((lane >> 3) & 1) * 4;

    float acc[2][8][4] = {};

    conv_fill(smb, row0, co0, 0, tid, gwh, gwl);

    const int NITER = K9 / 32;
    for (int it = 0; it < NITER; it++) {
        const int s = it & 1;
        asm volatile("cp.async.wait_group 0;" ::: "memory");
        __syncthreads();
        if (it + 1 < NITER)
            conv_fill(smb + (1 - s) * STG_BYTES, row0, co0, (it + 1) * 32, tid, gwh, gwl);

        const uint32_t base = smb + s * STG_BYTES;
        #pragma unroll
        for (int k16 = 0; k16 < 2; k16++) {
            const uint32_t ko = k16 * 8;
            uint32_t ah[2][4], al[2][4];
            #pragma unroll
            for (int mt = 0; mt < 2; mt++) {
                uint32_t aw = base + ((rbase + mt * 16 + aRow) * LDK2 + aCol + ko) * 4;
                ldsm4(ah[mt][0], ah[mt][1], ah[mt][2], ah[mt][3], aw);
                ldsm4(al[mt][0], al[mt][1], al[mt][2], al[mt][3], aw + 10240);
            }
            #pragma unroll
            for (int pr = 0; pr < 4; pr++) {
                uint32_t bw = base + 20480 +
                              ((cbase + pr * 16 + bRow) * LDK2 + bCol + ko) * 4;
                uint32_t bh0, bh1, bh2, bh3, bl0, bl1, bl2, bl3;
                ldsm4(bh0, bh1, bh2, bh3, bw);
                ldsm4(bl0, bl1, bl2, bl3, bw + 10240);
                mma_f16(acc[0][2 * pr],     ah[0], bh0, bh1);
                mma_f16(acc[1][2 * pr],     ah[1], bh0, bh1);
                mma_f16(acc[0][2 * pr + 1], ah[0], bh2, bh3);
                mma_f16(acc[1][2 * pr + 1], ah[1], bh2, bh3);
                mma_f16(acc[0][2 * pr],     ah[0], bl0, bl1);
                mma_f16(acc[1][2 * pr],     ah[1], bl0, bl1);
                mma_f16(acc[0][2 * pr + 1], ah[0], bl2, bl3);
                mma_f16(acc[1][2 * pr + 1], ah[1], bl2, bl3);
                mma_f16(acc[0][2 * pr],     al[0], bh0, bh1);
                mma_f16(acc[1][2 * pr],     al[1], bh0, bh1);
                mma_f16(acc[0][2 * pr + 1], al[0], bh2, bh3);
                mma_f16(acc[1][2 * pr + 1], al[1], bh2, bh3);
            }
        }
    }

    #pragma unroll
    for (int mt = 0; mt < 2; mt++) {
        #pragma unroll
        for (int nt = 0; nt < 8; nt++) {
            #pragma unroll
            for (int cp = 0; cp < 4; cp++) {
                int row = row0 + rbase + mt * 16 + lg + ((cp >= 2) ? 8 : 0);
                int col = cbase + nt * 8 + lt * 2 + (cp & 1);
                int co  = co0 + col;
                float v = acc[mt][nt][cp] + bias[co];
                int n = row >> 6, sp = row & 63;
                out[((size_t)n * 512 + co) * 64 + sp] = v;
            }
        }
    }
}

// ---------------------------------------------------------------------------
// Fused QK + dual softmax + agent blend (unchanged from R11).
// ---------------------------------------------------------------------------
#define FA_SMEM 136192
#define SST 388
#define QH_OFF 24832
#define QL_OFF 27136
#define KH_OFF 29440
#define KL_OFF 31744

__global__ void __launch_bounds__(256, 1)
fused_qk_softmax_kernel(const float* __restrict__ am, const int* __restrict__ agent)
{
    extern __shared__ uint32_t sm[];
    float* Sf = (float*)sm;
    const uint32_t smb = (uint32_t)__cvta_generic_to_shared(sm);

    const int m0 = blockIdx.x * 64;
    const int bp = blockIdx.y;
    const int head = bp >> 6;
    const int tid = threadIdx.x, lane = tid & 31, wid = tid >> 5;
    const int wq = (wid & 3) * 16;
    const int wc = (wid >> 2) * 32;
    const int lg = lane >> 2, lt = lane & 3;
    const int aRow = lane & 15, aCol = (lane >> 4) * 4;
    const int bRow = ((lane >> 4) & 1) * 8 + (lane & 7);
    const int bCol = ((lane >> 3) & 1) * 4;

    for (int v = 0; v < 2; v++) {
        const uint32_t* Q = g_feats_hl + (((size_t)(2 + v) * BP + bp) * SEQ + m0) * HD;
        #pragma unroll
        for (int i = 0; i < 4; i++) {
            int lin = i * 256 + tid;
            int row = lin >> 4, q4 = lin & 15;
            uint4 w = *(const uint4*)(Q + (size_t)row * HD + q4 * 4);
            int o = row * 36 + q4 * 2;
            *(uint2*)&sm[QH_OFF + o] = make_uint2(__byte_perm(w.x, w.y, 0x5410),
                                                  __byte_perm(w.z, w.w, 0x5410));
            *(uint2*)&sm[QL_OFF + o] = make_uint2(__byte_perm(w.x, w.y, 0x7632),
                                                  __byte_perm(w.z, w.w, 0x7632));
        }

        const uint32_t* Kv = g_feats_hl + ((size_t)v * BP + bp) * SEQ * HD;
        for (int kc = 0; kc < 6; kc++) {
            __syncthreads();
            #pragma unroll
            for (int i = 0; i < 4; i++) {
                int lin = i * 256 + tid;
                int row = lin >> 4, q4 = lin & 15;
                uint4 w = *(const uint4*)(Kv + (size_t)(kc * 64 + row) * HD + q4 * 4);
                int o = row * 36 + q4 * 2;
                *(uint2*)&sm[KH_OFF + o] = make_uint2(__byte_perm(w.x, w.y, 0x5410),
                                                      __byte_perm(w.z, w.w, 0x5410));
                *(uint2*)&sm[KL_OFF + o] = make_uint2(__byte_perm(w.x, w.y, 0x7632),
                                                      __byte_perm(w.z, w.w, 0x7632));
            }
            __syncthreads();

            float acc[4][4] = {};
            #pragma unroll
            for (int k16 = 0; k16 < 4; k16++) {
                const int ko = k16 * 8;
                uint32_t ah[4], al[4];
                uint32_t aw = smb + (QH_OFF + (wq + aRow) * 36 + aCol + ko) * 4;
                ldsm4(ah[0], ah[1], ah[2], ah[3], aw);
                ldsm4(al[0], al[1], al[2], al[3], aw + (QL_OFF - QH_OFF) * 4);
                #pragma unroll
                for (int pr = 0; pr < 2; pr++) {
                    uint32_t bw = smb + (KH_OFF + (wc + pr * 16 + bRow) * 36 + bCol + ko) * 4;
                    uint32_t bh0, bh1, bh2, bh3, bl0, bl1, bl2, bl3;
                    ldsm4(bh0, bh1, bh2, bh3, bw);
                    ldsm4(bl0, bl1, bl2, bl3, bw + (KL_OFF - KH_OFF) * 4);
                    mma_f16(acc[pr * 2],     ah, bh0, bh1);
                    mma_f16(acc[pr * 2],     ah, bl0, bl1);
                    mma_f16(acc[pr * 2],     al, bh0, bh1);
                    mma_f16(acc[pr * 2 + 1], ah, bh2, bh3);
                    mma_f16(acc[pr * 2 + 1], ah, bl2, bl3);
                    mma_f16(acc[pr * 2 + 1], al, bh2, bh3);
                }
            }
            #pragma unroll
            for (int nt = 0; nt < 4; nt++) {
                #pragma unroll
                for (int cp = 0; cp < 4; cp++) {
                    int q   = wq + lg + ((cp >= 2) ? 8 : 0);
                    int col = kc * 64 + wc + nt * 8 + lt * 2 + (cp & 1);
                    Sf[q * SST + col] = acc[nt][cp];
                }
            }
        }
        __syncthreads();

        #pragma unroll
        for (int r8 = 0; r8 < 8; r8++) {
            int row = wid * 8 + r8;
            int gq  = m0 + row;
            const float* amr = am + ((size_t)head * SEQ + gq) * SEQ;
            float e[12];
            float M = -1e30f;
            #pragma unroll
            for (int j = 0; j < 12; j++) {
                float s = Sf[row * SST + lane + 32 * j] * 0.125f + amr[lane + 32 * j];
                e[j] = s;
                M = fmaxf(M, s);
            }
            #pragma unroll
            for (int o = 16; o; o >>= 1) M = fmaxf(M, __shfl_xor_sync(~0u, M, o));
            float Z = 0.f;
            #pragma unroll
            for (int j = 0; j < 12; j++) { e[j] = __expf(e[j] - M); Z += e[j]; }
            #pragma unroll
            for (int o = 16; o; o >>= 1) Z += __shfl_xor_sync(~0u, Z, o);
            float rz = 1.f / Z;

            uint32_t* arow = g_attn + ((size_t)bp * SEQ + gq) * SEQ;
            if (v == 0) {
                #pragma unroll
                for (int j = 0; j < 12; j++)
                    arow[lane + 32 * j] = split_h2(e[j] * rz);
            } else {
                const int* mr = agent + ((size_t)head * SEQ + gq) * SEQ;
                #pragma unroll
                for (int j = 0; j < 12; j++) {
                    float a_same = unsplit_h2(arow[lane + 32 * j]);
                    float m = (float)mr[lane + 32 * j];
                    arow[lane + 32 * j] =
                        split_h2(m * a_same + (1.f - m) * e[j] * rz);
                }
            }
        }
    }
}

// ---------------------------------------------------------------------------
// AV on fp16x3 MMA (unchanged from R11).
// ---------------------------------------------------------------------------
#define AV_SMEM (13824 * 4)

__global__ void __launch_bounds__(256, 2)
av_mma_kernel()
{
    extern __shared__ uint32_t sm[];
    const uint32_t smb = (uint32_t)__cvta_generic_to_shared(sm);

    const int bp = blockIdx.y, m0 = blockIdx.x * 128;
    const int hh = bp >> 6, p = bp & 63;
    const int tid = threadIdx.x, lane = tid & 31, wid = tid >> 5;
    const int rbase = (wid & 3) * 32, cbase = (wid >> 2) * 32;
    const int lg = lane >> 2, lt = lane & 3;
    const int aRow = lane & 15, aCol = (lane >> 4) * 4;
    const int bRow = ((lane >> 4) & 1) * 8 + (lane & 7);
    const int bCol = ((lane >> 3) & 1) * 4;

    const uint32_t* A = g_attn + (size_t)bp * SS2 + (size_t)m0 * SEQ;
    const uint32_t* V = g_vT + (size_t)bp * HD * SEQ;

    float acc[2][4][4] = {};

    for (int ks = 0; ks < 6; ks++) {
        const int k0 = ks * 64;
        __syncthreads();
        #pragma unroll
        for (int i = 0; i < 16; i++) {
            int lin = i * 256 + tid;
            int row = lin >> 5, p2 = lin & 31;
            uint2 w = *(const uint2*)(A + (size_t)row * SEQ + k0 + p2 * 2);
            sm[row * 36 + p2]        = __byte_perm(w.x, w.y, 0x5410);
            sm[4608 + row * 36 + p2] = __byte_perm(w.x, w.y, 0x7632);
        }
        #pragma unroll
        for (int i = 0; i < 8; i++) {
            int lin = i * 256 + tid;
            int row = lin >> 5, p2 = lin & 31;
            uint2 w = *(const uint2*)(V + (size_t)row * SEQ + k0 + p2 * 2);
            sm[9216 + row * 36 + p2]  = __byte_perm(w.x, w.y, 0x5410);
            sm[11520 + row * 36 + p2] = __byte_perm(w.x, w.y, 0x7632);
        }
        __syncthreads();

        #pragma unroll
        for (int k16 = 0; k16 < 4; k16++) {
            const int ko = k16 * 8;
            uint32_t ah[2][4], al[2][4];
            #pragma unroll
            for (int mt = 0; mt < 2; mt++) {
                uint32_t aw = smb + ((rbase + mt * 16 + aRow) * 36 + aCol + ko) * 4;
                ldsm4(ah[mt][0], ah[mt][1], ah[mt][2], ah[mt][3], aw);
                ldsm4(al[mt][0], al[mt][1], al[mt][2], al[mt][3], aw + 18432);
            }
            #pragma unroll
            for (int pr = 0; pr < 2; pr++) {
                uint32_t bw = smb + 36864 + ((cbase + pr * 16 + bRow) * 36 + bCol + ko) * 4;
                uint32_t bh0, bh1, bh2, bh3, bl0, bl1, bl2, bl3;
                ldsm4(bh0, bh1, bh2, bh3, bw);
                ldsm4(bl0, bl1, bl2, bl3, bw + 9216);
                #pragma unroll
                for (int mt = 0; mt < 2; mt++) {
                    mma_f16(acc[mt][2 * pr],     ah[mt], bh0, bh1);
                    mma_f16(acc[mt][2 * pr],     ah[mt], bl0, bl1);
                    mma_f16(acc[mt][2 * pr],     al[mt], bh0, bh1);
                    mma_f16(acc[mt][2 * pr + 1], ah[mt], bh2, bh3);
                    mma_f16(acc[mt][2 * pr + 1], ah[mt], bl2, bl3);
                    mma_f16(acc[mt][2 * pr + 1], al[mt], bh2, bh3);
                }
            }
        }
    }

    #pragma unroll
    for (int mt = 0; mt < 2; mt++) {
        #pragma unroll
        for (int nt = 0; nt < 4; nt++) {
            #pragma unroll
            for (int cp = 0; cp < 4; cp++) {
                int q  = m0 + rbase + mt * 16 + lg + ((cp >= 2) ? 8 : 0);
                int dd = cbase + nt * 8 + lt * 2 + (cp & 1);
                g_c2_hl[((size_t)q * CIN + (dd * 8 + hh)) * 64 + p] =
                    split_h2(acc[mt][nt][cp]);
            }
        }
    }
}

// ---------------------------------------------------------------------------
extern "C" void kernel_launch(void* const* d_in, const int* in_sizes, int n_in,
                              void* d_out, int out_size)
{
    const float* inp       = (const float*)d_in[0];
    const float* attn_mask = (const float*)d_in[1];
    const int*   agent     = (const int*)  d_in[2];
    const float* w_in      = (const float*)d_in[3];
    const float* b_in      = (const float*)d_in[4];
    const float* w_out     = (const float*)d_in[5];
    const float* b_out     = (const float*)d_in[6];
    float*       out       = (float*)d_out;

    __half *wh_out, *wl_out;
    cudaGetSymbolAddress((void**)&wh_out, g_wh_out);
    cudaGetSymbolAddress((void**)&wl_out, g_wl_out);

    cudaFuncSetAttribute(wino_gemm_kernel,
                         cudaFuncAttributeMaxDynamicSharedMemorySize, SMEM_BYTES);
    cudaFuncSetAttribute(wino_out_kernel,
                         cudaFuncAttributeMaxDynamicSharedMemorySize, WO_SMEM);
    cudaFuncSetAttribute(conv_f16_kernel,
                         cudaFuncAttributeMaxDynamicSharedMemorySize, SMEM_BYTES);
    cudaFuncSetAttribute(fused_qk_softmax_kernel,
                         cudaFuncAttributeMaxDynamicSharedMemorySize, FA_SMEM);
    cudaFuncSetAttribute(av_mma_kernel,
                         cudaFuncAttributeMaxDynamicSharedMemorySize, AV_SMEM);

    // conv_out weight split (k'-permuted dense path)
    const int n_wout = 512 * K9;
    split_w_kernel<<<(n_wout + 255) / 256, 256>>>(w_out, wh_out, wl_out, n_wout);

    // Winograd conv_in: weight + input transforms
    wino_w_kernel<<<(NCO * CIN + 255) / 256, 256>>>(w_in);
    wino_in_kernel<<<dim3(SEQ, 8), 256>>>(inp);

    // 16 transform-domain GEMMs: M = V @ U^T
    wino_gemm_kernel<<<dim3(20, 48, 16), 256, SMEM_BYTES>>>();

    // Output transform + bias + scatter to attention layouts
    wino_out_kernel<<<dim3(SEQ, 40), 256, WO_SMEM>>>(b_in);

    // fused scores + dual softmax + agent blend -> packed attn
    fused_qk_softmax_kernel<<<dim3(6, BP), 256, FA_SMEM>>>(attn_mask, agent);

    // attn @ V on tensor cores -> packed conv2 input
    av_mma_kernel<<<dim3(3, BP), 256, AV_SMEM>>>();

    // im2col expansion of attention output (packed source)
    im2col_kernel<<<dim3(SEQ, 8), 256>>>();

    // conv_out GEMM (dense fp16x3)
    conv_f16_kernel<<<dim3(4, 192), 256, SMEM_BYTES>>>(wh_out, wl_out, b_out, out);
}

// round 13
// speedup vs baseline: 1.0345x; 1.0345x over previous
#include <cuda_runtime.h>
#include <cuda_fp16.h>
#include <cstdint>

#define SEQ 384
#define CIN 512
#define HW  64
#define NH  8
#define HD  64
#define K9  (CIN * 9)        // 4608
#define BP  512              // NH * HW batch-pairs
#define NROWS (SEQ * HW)     // 24576 GEMM rows
#define SS2 (SEQ * SEQ)      // 147456

// Scratch (device globals; no runtime allocation)
__device__ uint32_t g_feats_hl[(size_t)4 * BP * SEQ * HD];  // [e][bp][n][dd] packed(hi,lo)
__device__ uint32_t g_vT[(size_t)BP * HD * SEQ];            // [bp][dd][n]   packed(hi,lo)
__device__ uint32_t g_attn[(size_t)BP * SS2];               // blended attn, packed(hi,lo)
__device__ uint32_t g_c2_hl[(size_t)SEQ * CIN * HW];        // conv2 input, packed(hi,lo)
__device__ __half   g_Ah[(size_t)NROWS * K9];               // im2col hi plane (k' = r*512+ci)
__device__ __half   g_Al[(size_t)NROWS * K9];               // im2col lo plane
__device__ __half   g_wh_in[(size_t)2560 * K9];             // weights hi, k'-order
__device__ __half   g_wl_in[(size_t)2560 * K9];
__device__ __half   g_wh_out[(size_t)512 * K9];
__device__ __half   g_wl_out[(size_t)512 * K9];

// ---------------------------------------------------------------------------
// helpers
// ---------------------------------------------------------------------------
__device__ __forceinline__ uint32_t split_h2(float x)
{
    __half hi = __float2half_rn(x);
    __half lo = __float2half_rn(x - __half2float(hi));
    return (uint32_t)__half_as_ushort(hi) | ((uint32_t)__half_as_ushort(lo) << 16);
}
__device__ __forceinline__ float unsplit_h2(uint32_t p)
{
    return __half2float(__ushort_as_half((unsigned short)(p & 0xFFFF)))
         + __half2float(__ushort_as_half((unsigned short)(p >> 16)));
}

__device__ __forceinline__ void mma_f16(float c[4], const uint32_t a[4],
                                        uint32_t b0, uint32_t b1)
{
    asm volatile(
        "mma.sync.aligned.m16n8k16.row.col.f32.f16.f16.f32 "
        "{%0,%1,%2,%3}, {%4,%5,%6,%7}, {%8,%9}, {%0,%1,%2,%3};"
        : "+f"(c[0]), "+f"(c[1]), "+f"(c[2]), "+f"(c[3])
        : "r"(a[0]), "r"(a[1]), "r"(a[2]), "r"(a[3]), "r"(b0), "r"(b1));
}
__device__ __forceinline__ void ldsm4(uint32_t& r0, uint32_t& r1, uint32_t& r2,
                                      uint32_t& r3, uint32_t addr)
{
    asm volatile("ldmatrix.sync.aligned.m8n8.x4.shared.b16 {%0,%1,%2,%3}, [%4];"
                 : "=r"(r0), "=r"(r1), "=r"(r2), "=r"(r3) : "r"(addr));
}
__device__ __forceinline__ void cpa16(uint32_t dst, const void* src)
{
    asm volatile("cp.async.cg.shared.global [%0], [%1], 16;" :: "r"(dst), "l"(src));
}

// ---------------------------------------------------------------------------
// Weight split + permute to k' = r*512 + ci order
// ---------------------------------------------------------------------------
__global__ void split_w_kernel(const float* __restrict__ w,
                               __half* __restrict__ wh, __half* __restrict__ wl, int n)
{
    int i = blockIdx.x * 256 + threadIdx.x;
    if (i >= n) return;
    int co = i / K9;
    int kn = i - co * K9;
    int r = kn >> 9, ci = kn & 511;
    float x = w[(size_t)co * K9 + ci * 9 + r];
    __half hi = __float2half_rn(x);
    wh[i] = hi;
    wl[i] = __float2half_rn(x - __half2float(hi));
}

// ---------------------------------------------------------------------------
// im2col expansion into hi/lo fp16 planes, k' = r*512 + ci.
// ---------------------------------------------------------------------------
template <bool PACKED>
__global__ __launch_bounds__(256) void im2col_kernel(const float* __restrict__ srcF)
{
    __shared__ ushort th[64][72];
    __shared__ ushort tl[64][72];
    const int n   = blockIdx.x;
    const int ci0 = blockIdx.y * 64;
    const int t   = threadIdx.x;

    {
        int sp4 = (t & 15) * 4;
        int ciL = t >> 4;
        #pragma unroll
        for (int pass = 0; pass < 4; pass++) {
            int ci = pass * 16 + ciL;
            if (PACKED) {
                uint4 w = *(const uint4*)(g_c2_hl + ((size_t)n * CIN + ci0 + ci) * 64 + sp4);
                uint32_t ws[4] = {w.x, w.y, w.z, w.w};
                #pragma unroll
                for (int j = 0; j < 4; j++) {
                    th[sp4 + j][ci] = (ushort)(ws[j] & 0xFFFF);
                    tl[sp4 + j][ci] = (ushort)(ws[j] >> 16);
                }
            } else {
                float4 v = *(const float4*)(srcF + ((size_t)n * CIN + ci0 + ci) * 64 + sp4);
                float vs[4] = {v.x, v.y, v.z, v.w};
                #pragma unroll
                for (int j = 0; j < 4; j++) {
                    __half hi = __float2half_rn(vs[j]);
                    __half lo = __float2half_rn(vs[j] - __half2float(hi));
                    th[sp4 + j][ci] = __half_as_ushort(hi);
                    tl[sp4 + j][ci] = __half_as_ushort(lo);
                }
            }
        }
    }
    __syncthreads();

    const int ciQ = t & 15;
    const int rg  = t >> 4;
    #pragma unroll
    for (int si = 0; si < 4; si++) {
        int sp = si * 16 + rg;
        int yy = sp >> 3, xx = sp & 7;
        size_t obase = (size_t)(n * 64 + sp) * K9 + ci0 + ciQ * 4;
        #pragma unroll
        for (int r = 0; r < 9; r++) {
            int y = yy + r / 3 - 1, x = xx + r % 3 - 1;
            uint2 vh = make_uint2(0, 0), vl = make_uint2(0, 0);
            if ((unsigned)y < 8u && (unsigned)x < 8u) {
                int spp = y * 8 + x;
                vh = *(const uint2*)&th[spp][ciQ * 4];
                vl = *(const uint2*)&tl[spp][ciQ * 4];
            }
            *(uint2*)&g_Ah[obase + (size_t)r * 512] = vh;
            *(uint2*)&g_Al[obase + (size_t)r * 512] = vl;
        }
    }
}

// ---------------------------------------------------------------------------
// fp16x3 GEMM conv (R11 form: 128x128, 256 thr, 2-stage cp.async,
// term-major MMA order, single barrier per stage).
// ---------------------------------------------------------------------------
#define LDK2 20
#define STG_BYTES (4 * 128 * LDK2 * 4)
#define SMEM_BYTES (2 * STG_BYTES)

__device__ __forceinline__ void conv_fill(uint32_t base, int row0, int co0, int k0,
                                          int tid, const __half* gwh, const __half* gwl)
{
    #pragma unroll
    for (int h = 0; h < 2; h++) {
        int c = h * 256 + tid;
        int row = c >> 2, q = c & 3;
        uint32_t doff = (uint32_t)((row * LDK2 + q * 4) * 4);
        size_t aoff = (size_t)(row0 + row) * K9 + k0 + q * 8;
        size_t boff = (size_t)(co0 + row) * K9 + k0 + q * 8;
        cpa16(base + doff,         g_Ah + aoff);
        cpa16(base + 10240 + doff, g_Al + aoff);
        cpa16(base + 20480 + doff, gwh + boff);
        cpa16(base + 30720 + doff, gwl + boff);
    }
    asm volatile("cp.async.commit_group;" ::: "memory");
}

template <int CO, bool FIRST>
__global__ void __launch_bounds__(256, 2)
conv_f16_kernel(const __half* __restrict__ gwh,
                const __half* __restrict__ gwl,
                const float* __restrict__ bias,
                float* __restrict__ out)
{
    extern __shared__ uint32_t sm[];
    const uint32_t smb = (uint32_t)__cvta_generic_to_shared(sm);

    const int row0 = blockIdx.y * 128;
    const int co0  = blockIdx.x * 128;
    const int tid  = threadIdx.x;
    const int lane = tid & 31, wid = tid >> 5;
    const int rbase = (wid >> 1) * 32;
    const int cbase = (wid & 1) * 64;
    const int lg = lane >> 2, lt = lane & 3;

    const int aRow = lane & 15, aCol = (lane >> 4) * 4;
    const int bRow = ((lane >> 4) & 1) * 8 + (lane & 7);
    const int bCol = ((lane >> 3) & 1) * 4;

    float acc[2][8][4] = {};

    conv_fill(smb, row0, co0, 0, tid, gwh, gwl);

    const int NITER = K9 / 32;
    for (int it = 0; it < NITER; it++) {
        const int s = it & 1;
        asm volatile("cp.async.wait_group 0;" ::: "memory");
        __syncthreads();
        if (it + 1 < NITER)
            conv_fill(smb + (1 - s) * STG_BYTES, row0, co0, (it + 1) * 32, tid, gwh, gwl);

        const uint32_t base = smb + s * STG_BYTES;
        #pragma unroll
        for (int k16 = 0; k16 < 2; k16++) {
            const uint32_t ko = k16 * 8;
            uint32_t ah[2][4], al[2][4];
            #pragma unroll
            for (int mt = 0; mt < 2; mt++) {
                uint32_t aw = base + ((rbase + mt * 16 + aRow) * LDK2 + aCol + ko) * 4;
                ldsm4(ah[mt][0], ah[mt][1], ah[mt][2], ah[mt][3], aw);
                ldsm4(al[mt][0], al[mt][1], al[mt][2], al[mt][3], aw + 10240);
            }
            #pragma unroll
            for (int pr = 0; pr < 4; pr++) {
                uint32_t bw = base + 20480 +
                              ((cbase + pr * 16 + bRow) * LDK2 + bCol + ko) * 4;
                uint32_t bh0, bh1, bh2, bh3, bl0, bl1, bl2, bl3;
                ldsm4(bh0, bh1, bh2, bh3, bw);
                ldsm4(bl0, bl1, bl2, bl3, bw + 10240);
                mma_f16(acc[0][2 * pr],     ah[0], bh0, bh1);
                mma_f16(acc[1][2 * pr],     ah[1], bh0, bh1);
                mma_f16(acc[0][2 * pr + 1], ah[0], bh2, bh3);
                mma_f16(acc[1][2 * pr + 1], ah[1], bh2, bh3);
                mma_f16(acc[0][2 * pr],     ah[0], bl0, bl1);
                mma_f16(acc[1][2 * pr],     ah[1], bl0, bl1);
                mma_f16(acc[0][2 * pr + 1], ah[0], bl2, bl3);
                mma_f16(acc[1][2 * pr + 1], ah[1], bl2, bl3);
                mma_f16(acc[0][2 * pr],     al[0], bh0, bh1);
                mma_f16(acc[1][2 * pr],     al[1], bh0, bh1);
                mma_f16(acc[0][2 * pr + 1], al[0], bh2, bh3);
                mma_f16(acc[1][2 * pr + 1], al[1], bh2, bh3);
            }
        }
    }

    // ---- epilogue ----
    #pragma unroll
    for (int mt = 0; mt < 2; mt++) {
        #pragma unroll
        for (int nt = 0; nt < 8; nt++) {
            #pragma unroll
            for (int cp = 0; cp < 4; cp++) {
                int row = row0 + rbase + mt * 16 + lg + ((cp >= 2) ? 8 : 0);
                int col = cbase + nt * 8 + lt * 2 + (cp & 1);
                int co  = co0 + col;
                float v = acc[mt][nt][cp] + bias[co];
                int n = row >> 6, sp = row & 63;
                if (FIRST) {
                    int e  = co >> 9;
                    int dd = (co >> 3) & 63;
                    int hh = co & 7;
                    int bpi = hh * 64 + sp;
                    uint32_t pv = split_h2(v);
                    if (e < 4)
                        g_feats_hl[(((size_t)e * BP + bpi) * SEQ + n) * HD + dd] = pv;
                    else
                        g_vT[((size_t)bpi * HD + dd) * SEQ + n] = pv;
                } else {
                    out[((size_t)n * CO + co) * 64 + sp] = v;
                }
            }
        }
    }
}

// ---------------------------------------------------------------------------
// Fused QK + dual softmax + agent blend, 32-row q-tiles, 2 CTAs/SM.
// Grid (12 qtiles, 512 bp), 256 threads. Warp layout: 2 q-bands (16 rows) x
// 4 col-bands (16 cols) per 64-col K chunk. smem (words): S 0..12415
// (32x388 f32), Qh 12416, Ql 13568 (32x36 each), Kh 14720, Kl 17024
// (64x36 each). Total 19328 words = 77312 bytes -> 2 CTAs/SM.
// ---------------------------------------------------------------------------
#define FA_SMEM 77312
#define SST 388
#define QH_OFF 12416
#define QL_OFF 13568
#define KH_OFF 14720
#define KL_OFF 17024

__global__ void __launch_bounds__(256, 2)
fused_qk_softmax_kernel(const float* __restrict__ am, const int* __restrict__ agent)
{
    extern __shared__ uint32_t sm[];
    float* Sf = (float*)sm;
    const uint32_t smb = (uint32_t)__cvta_generic_to_shared(sm);

    const int m0 = blockIdx.x * 32;
    const int bp = blockIdx.y;
    const int head = bp >> 6;
    const int tid = threadIdx.x, lane = tid & 31, wid = tid >> 5;
    const int wq   = (wid & 1) * 16;    // q band (16 rows)
    const int wcol = (wid >> 1) * 16;   // col band within 64-col chunk
    const int lg = lane >> 2, lt = lane & 3;
    const int aRow = lane & 15, aCol = (lane >> 4) * 4;
    const int bRow = ((lane >> 4) & 1) * 8 + (lane & 7);
    const int bCol = ((lane >> 3) & 1) * 4;

    for (int v = 0; v < 2; v++) {
        // ---- stage Q (variant 2+v), rows m0..m0+31
        const uint32_t* Q = g_feats_hl + (((size_t)(2 + v) * BP + bp) * SEQ + m0) * HD;
        #pragma unroll
        for (int i = 0; i < 2; i++) {
            int lin = i * 256 + tid;              // 512 uint4 slots
            int row = lin >> 4, q4 = lin & 15;
            uint4 w = *(const uint4*)(Q + (size_t)row * HD + q4 * 4);
            int o = row * 36 + q4 * 2;
            *(uint2*)&sm[QH_OFF + o] = make_uint2(__byte_perm(w.x, w.y, 0x5410),
                                                  __byte_perm(w.z, w.w, 0x5410));
            *(uint2*)&sm[QL_OFF + o] = make_uint2(__byte_perm(w.x, w.y, 0x7632),
                                                  __byte_perm(w.z, w.w, 0x7632));
        }

        const uint32_t* Kv = g_feats_hl + ((size_t)v * BP + bp) * SEQ * HD;
        for (int kc = 0; kc < 6; kc++) {
            __syncthreads();   // K/S free (prev chunk MMA + prev softmax done)
            #pragma unroll
            for (int i = 0; i < 4; i++) {
                int lin = i * 256 + tid;          // 1024 uint4 slots
                int row = lin >> 4, q4 = lin & 15;
                uint4 w = *(const uint4*)(Kv + (size_t)(kc * 64 + row) * HD + q4 * 4);
                int o = row * 36 + q4 * 2;
                *(uint2*)&sm[KH_OFF + o] = make_uint2(__byte_perm(w.x, w.y, 0x5410),
                                                      __byte_perm(w.z, w.w, 0x5410));
                *(uint2*)&sm[KL_OFF + o] = make_uint2(__byte_perm(w.x, w.y, 0x7632),
                                                      __byte_perm(w.z, w.w, 0x7632));
            }
            __syncthreads();

            float acc[2][4] = {};
            #pragma unroll
            for (int k16 = 0; k16 < 4; k16++) {
                const int ko = k16 * 8;
                uint32_t ah[4], al[4];
                uint32_t aw = smb + (QH_OFF + (wq + aRow) * 36 + aCol + ko) * 4;
                ldsm4(ah[0], ah[1], ah[2], ah[3], aw);
                ldsm4(al[0], al[1], al[2], al[3], aw + (QL_OFF - QH_OFF) * 4);
                uint32_t bw = smb + (KH_OFF + (wcol + bRow) * 36 + bCol + ko) * 4;
                uint32_t bh0, bh1, bh2, bh3, bl0, bl1, bl2, bl3;
                ldsm4(bh0, bh1, bh2, bh3, bw);
                ldsm4(bl0, bl1, bl2, bl3, bw + (KL_OFF - KH_OFF) * 4);
                mma_f16(acc[0], ah, bh0, bh1);
                mma_f16(acc[1], ah, bh2, bh3);
                mma_f16(acc[0], ah, bl0, bl1);
                mma_f16(acc[1], ah, bl2, bl3);
                mma_f16(acc[0], al, bh0, bh1);
                mma_f16(acc[1], al, bh2, bh3);
            }
            #pragma unroll
            for (int nt = 0; nt < 2; nt++) {
                #pragma unroll
                for (int cp = 0; cp < 4; cp++) {
                    int q   = wq + lg + ((cp >= 2) ? 8 : 0);
                    int col = kc * 64 + wcol + nt * 8 + lt * 2 + (cp & 1);
                    Sf[q * SST + col] = acc[nt][cp];
                }
            }
        }
        __syncthreads();

        // ---- softmax: 4 rows per warp, scale+mask applied on read
        #pragma unroll
        for (int r4 = 0; r4 < 4; r4++) {
            int row = wid * 4 + r4;
            int gq  = m0 + row;
            const float* amr = am + ((size_t)head * SEQ + gq) * SEQ;
            float e[12];
            float M = -1e30f;
            #pragma unroll
            for (int j = 0; j < 12; j++) {
                float s = Sf[row * SST + lane + 32 * j] * 0.125f + amr[lane + 32 * j];
                e[j] = s;
                M = fmaxf(M, s);
            }
            #pragma unroll
            for (int o = 16; o; o >>= 1) M = fmaxf(M, __shfl_xor_sync(~0u, M, o));
            float Z = 0.f;
            #pragma unroll
            for (int j = 0; j < 12; j++) { e[j] = __expf(e[j] - M); Z += e[j]; }
            #pragma unroll
            for (int o = 16; o; o >>= 1) Z += __shfl_xor_sync(~0u, Z, o);
            float rz = 1.f / Z;

            uint32_t* arow = g_attn + ((size_t)bp * SEQ + gq) * SEQ;
            if (v == 0) {
                #pragma unroll
                for (int j = 0; j < 12; j++)
                    arow[lane + 32 * j] = split_h2(e[j] * rz);
            } else {
                const int* mr = agent + ((size_t)head * SEQ + gq) * SEQ;
                #pragma unroll
                for (int j = 0; j < 12; j++) {
                    float a_same = unsplit_h2(arow[lane + 32 * j]);
                    float m = (float)mr[lane + 32 * j];
                    arow[lane + 32 * j] =
                        split_h2(m * a_same + (1.f - m) * e[j] * rz);
                }
            }
        }
        // Q refill for v=1 touches only QH/QL (disjoint from Sf being read by
        // softmax); all Q(v=0) reads ended before the pre-softmax barrier.
    }
}

// ---------------------------------------------------------------------------
// AV on fp16x3 MMA (unchanged from R11).
// ---------------------------------------------------------------------------
#define AV_SMEM (13824 * 4)

__global__ void __launch_bounds__(256, 2)
av_mma_kernel()
{
    extern __shared__ uint32_t sm[];
    const uint32_t smb = (uint32_t)__cvta_generic_to_shared(sm);

    const int bp = blockIdx.y, m0 = blockIdx.x * 128;
    const int hh = bp >> 6, p = bp & 63;
    const int tid = threadIdx.x, lane = tid & 31, wid = tid >> 5;
    const int rbase = (wid & 3) * 32, cbase = (wid >> 2) * 32;
    const int lg = lane >> 2, lt = lane & 3;
    const int aRow = lane & 15, aCol = (lane >> 4) * 4;
    const int bRow = ((lane >> 4) & 1) * 8 + (lane & 7);
    const int bCol = ((lane >> 3) & 1) * 4;

    const uint32_t* A = g_attn + (size_t)bp * SS2 + (size_t)m0 * SEQ;
    const uint32_t* V = g_vT + (size_t)bp * HD * SEQ;

    float acc[2][4][4] = {};

    for (int ks = 0; ks < 6; ks++) {
        const int k0 = ks * 64;
        __syncthreads();
        #pragma unroll
        for (int i = 0; i < 16; i++) {
            int lin = i * 256 + tid;
            int row = lin >> 5, p2 = lin & 31;
            uint2 w = *(const uint2*)(A + (size_t)row * SEQ + k0 + p2 * 2);
            sm[row * 36 + p2]        = __byte_perm(w.x, w.y, 0x5410);
            sm[4608 + row * 36 + p2] = __byte_perm(w.x, w.y, 0x7632);
        }
        #pragma unroll
        for (int i = 0; i < 8; i++) {
            int lin = i * 256 + tid;
            int row = lin >> 5, p2 = lin & 31;
            uint2 w = *(const uint2*)(V + (size_t)row * SEQ + k0 + p2 * 2);
            sm[9216 + row * 36 + p2]  = __byte_perm(w.x, w.y, 0x5410);
            sm[11520 + row * 36 + p2] = __byte_perm(w.x, w.y, 0x7632);
        }
        __syncthreads();

        #pragma unroll
        for (int k16 = 0; k16 < 4; k16++) {
            const int ko = k16 * 8;
            uint32_t ah[2][4], al[2][4];
            #pragma unroll
            for (int mt = 0; mt < 2; mt++) {
                uint32_t aw = smb + ((rbase + mt * 16 + aRow) * 36 + aCol + ko) * 4;
                ldsm4(ah[mt][0], ah[mt][1], ah[mt][2], ah[mt][3], aw);
                ldsm4(al[mt][0], al[mt][1], al[mt][2], al[mt][3], aw + 18432);
            }
            #pragma unroll
            for (int pr = 0; pr < 2; pr++) {
                uint32_t bw = smb + 36864 + ((cbase + pr * 16 + bRow) * 36 + bCol + ko) * 4;
                uint32_t bh0, bh1, bh2, bh3, bl0, bl1, bl2, bl3;
                ldsm4(bh0, bh1, bh2, bh3, bw);
                ldsm4(bl0, bl1, bl2, bl3, bw + 9216);
                #pragma unroll
                for (int mt = 0; mt < 2; mt++) {
                    mma_f16(acc[mt][2 * pr],     ah[mt], bh0, bh1);
                    mma_f16(acc[mt][2 * pr],     ah[mt], bl0, bl1);
                    mma_f16(acc[mt][2 * pr],     al[mt], bh0, bh1);
                    mma_f16(acc[mt][2 * pr + 1], ah[mt], bh2, bh3);
                    mma_f16(acc[mt][2 * pr + 1], ah[mt], bl2, bl3);
                    mma_f16(acc[mt][2 * pr + 1], al[mt], bh2, bh3);
                }
            }
        }
    }

    #pragma unroll
    for (int mt = 0; mt < 2; mt++) {
        #pragma unroll
        for (int nt = 0; nt < 4; nt++) {
            #pragma unroll
            for (int cp = 0; cp < 4; cp++) {
                int q  = m0 + rbase + mt * 16 + lg + ((cp >= 2) ? 8 : 0);
                int dd = cbase + nt * 8 + lt * 2 + (cp & 1);
                g_c2_hl[((size_t)q * CIN + (dd * 8 + hh)) * 64 + p] =
                    split_h2(acc[mt][nt][cp]);
            }
        }
    }
}

// ---------------------------------------------------------------------------
extern "C" void kernel_launch(void* const* d_in, const int* in_sizes, int n_in,
                              void* d_out, int out_size)
{
    const float* inp       = (const float*)d_in[0];
    const float* attn_mask = (const float*)d_in[1];
    const int*   agent     = (const int*)  d_in[2];
    const float* w_in      = (const float*)d_in[3];
    const float* b_in      = (const float*)d_in[4];
    const float* w_out     = (const float*)d_in[5];
    const float* b_out     = (const float*)d_in[6];
    float*       out       = (float*)d_out;

    __half *wh_in, *wl_in, *wh_out, *wl_out;
    cudaGetSymbolAddress((void**)&wh_in,  g_wh_in);
    cudaGetSymbolAddress((void**)&wl_in,  g_wl_in);
    cudaGetSymbolAddress((void**)&wh_out, g_wh_out);
    cudaGetSymbolAddress((void**)&wl_out, g_wl_out);

    cudaFuncSetAttribute(conv_f16_kernel<2560, true>,
                         cudaFuncAttributeMaxDynamicSharedMemorySize, SMEM_BYTES);
    cudaFuncSetAttribute(conv_f16_kernel<512, false>,
                         cudaFuncAttributeMaxDynamicSharedMemorySize, SMEM_BYTES);
    cudaFuncSetAttribute(fused_qk_softmax_kernel,
                         cudaFuncAttributeMaxDynamicSharedMemorySize, FA_SMEM);
    cudaFuncSetAttribute(av_mma_kernel,
                         cudaFuncAttributeMaxDynamicSharedMemorySize, AV_SMEM);

    const int n_win  = 2560 * K9;
    const int n_wout = 512 * K9;
    split_w_kernel<<<(n_win + 255) / 256, 256>>>(w_in, wh_in, wl_in, n_win);
    split_w_kernel<<<(n_wout + 255) / 256, 256>>>(w_out, wh_out, wl_out, n_wout);

    // im2col expansion of raw input
    im2col_kernel<false><<<dim3(SEQ, 8), 256>>>(inp);

    // conv_in GEMM: M = 24576 (192 blocks of 128), N = 2560 (20 tiles)
    conv_f16_kernel<2560, true><<<dim3(20, 192), 256, SMEM_BYTES>>>(wh_in, wl_in, b_in, nullptr);

    // fused scores + dual softmax + agent blend -> packed attn (32-row tiles)
    fused_qk_softmax_kernel<<<dim3(12, BP), 256, FA_SMEM>>>(attn_mask, agent);

    // attn @ V on tensor cores -> packed conv2 input
    av_mma_kernel<<<dim3(3, BP), 256, AV_SMEM>>>();

    // im2col expansion of attention output (packed source)
    im2col_kernel<true><<<dim3(SEQ, 8), 256>>>(nullptr);

    // conv_out GEMM: N = 512 (4 tiles)
    conv_f16_kernel<512, false><<<dim3(4, 192), 256, SMEM_BYTES>>>(wh_out, wl_out, b_out, out);
}

// round 14
// speedup vs baseline: 1.0397x; 1.0050x over previous
#include <cuda_runtime.h>
#include <cuda_fp16.h>
#include <cstdint>

#define SEQ 384
#define CIN 512
#define HW  64
#define NH  8
#define HD  64
#define K9  (CIN * 9)        // 4608
#define BP  512              // NH * HW batch-pairs
#define NROWS (SEQ * HW)     // 24576 GEMM rows
#define SS2 (SEQ * SEQ)      // 147456

// Scratch (device globals; no runtime allocation)
__device__ uint32_t g_feats_hl[(size_t)4 * BP * SEQ * HD];  // [e][bp][n][dd] packed(hi,lo)
__device__ uint32_t g_vT[(size_t)BP * HD * SEQ];            // [bp][dd][n]   packed(hi,lo)
__device__ uint32_t g_attn[(size_t)BP * SS2];               // blended attn, packed(hi,lo)
__device__ uint32_t g_c2_hl[(size_t)SEQ * CIN * HW];        // conv2 input, packed(hi,lo)
__device__ __half   g_Ah[(size_t)NROWS * K9];               // im2col hi plane (k' = r*512+ci)
__device__ __half   g_Al[(size_t)NROWS * K9];               // im2col lo plane
__device__ __half   g_wh_in[(size_t)2560 * K9];             // weights hi, k'-order
__device__ __half   g_wl_in[(size_t)2560 * K9];
__device__ __half   g_wh_out[(size_t)512 * K9];
__device__ __half   g_wl_out[(size_t)512 * K9];

// ---------------------------------------------------------------------------
// helpers
// ---------------------------------------------------------------------------
__device__ __forceinline__ uint32_t split_h2(float x)
{
    __half hi = __float2half_rn(x);
    __half lo = __float2half_rn(x - __half2float(hi));
    return (uint32_t)__half_as_ushort(hi) | ((uint32_t)__half_as_ushort(lo) << 16);
}
__device__ __forceinline__ float unsplit_h2(uint32_t p)
{
    return __half2float(__ushort_as_half((unsigned short)(p & 0xFFFF)))
         + __half2float(__ushort_as_half((unsigned short)(p >> 16)));
}

__device__ __forceinline__ void mma_f16(float c[4], const uint32_t a[4],
                                        uint32_t b0, uint32_t b1)
{
    asm volatile(
        "mma.sync.aligned.m16n8k16.row.col.f32.f16.f16.f32 "
        "{%0,%1,%2,%3}, {%4,%5,%6,%7}, {%8,%9}, {%0,%1,%2,%3};"
        : "+f"(c[0]), "+f"(c[1]), "+f"(c[2]), "+f"(c[3])
        : "r"(a[0]), "r"(a[1]), "r"(a[2]), "r"(a[3]), "r"(b0), "r"(b1));
}
__device__ __forceinline__ void ldsm4(uint32_t& r0, uint32_t& r1, uint32_t& r2,
                                      uint32_t& r3, uint32_t addr)
{
    asm volatile("ldmatrix.sync.aligned.m8n8.x4.shared.b16 {%0,%1,%2,%3}, [%4];"
                 : "=r"(r0), "=r"(r1), "=r"(r2), "=r"(r3) : "r"(addr));
}
__device__ __forceinline__ void cpa16(uint32_t dst, const void* src)
{
    asm volatile("cp.async.cg.shared.global [%0], [%1], 16;" :: "r"(dst), "l"(src));
}

// ---------------------------------------------------------------------------
// Weight split + permute to k' = r*512 + ci order
// ---------------------------------------------------------------------------
__global__ void split_w_kernel(const float* __restrict__ w,
                               __half* __restrict__ wh, __half* __restrict__ wl, int n)
{
    int i = blockIdx.x * 256 + threadIdx.x;
    if (i >= n) return;
    int co = i / K9;
    int kn = i - co * K9;
    int r = kn >> 9, ci = kn & 511;
    float x = w[(size_t)co * K9 + ci * 9 + r];
    __half hi = __float2half_rn(x);
    wh[i] = hi;
    wl[i] = __float2half_rn(x - __half2float(hi));
}

// ---------------------------------------------------------------------------
// im2col expansion into hi/lo fp16 planes, k' = r*512 + ci.
// ---------------------------------------------------------------------------
template <bool PACKED>
__global__ __launch_bounds__(256) void im2col_kernel(const float* __restrict__ srcF)
{
    __shared__ ushort th[64][72];
    __shared__ ushort tl[64][72];
    const int n   = blockIdx.x;
    const int ci0 = blockIdx.y * 64;
    const int t   = threadIdx.x;

    {
        int sp4 = (t & 15) * 4;
        int ciL = t >> 4;
        #pragma unroll
        for (int pass = 0; pass < 4; pass++) {
            int ci = pass * 16 + ciL;
            if (PACKED) {
                uint4 w = *(const uint4*)(g_c2_hl + ((size_t)n * CIN + ci0 + ci) * 64 + sp4);
                uint32_t ws[4] = {w.x, w.y, w.z, w.w};
                #pragma unroll
                for (int j = 0; j < 4; j++) {
                    th[sp4 + j][ci] = (ushort)(ws[j] & 0xFFFF);
                    tl[sp4 + j][ci] = (ushort)(ws[j] >> 16);
                }
            } else {
                float4 v = *(const float4*)(srcF + ((size_t)n * CIN + ci0 + ci) * 64 + sp4);
                float vs[4] = {v.x, v.y, v.z, v.w};
                #pragma unroll
                for (int j = 0; j < 4; j++) {
                    __half hi = __float2half_rn(vs[j]);
                    __half lo = __float2half_rn(vs[j] - __half2float(hi));
                    th[sp4 + j][ci] = __half_as_ushort(hi);
                    tl[sp4 + j][ci] = __half_as_ushort(lo);
                }
            }
        }
    }
    __syncthreads();

    const int ciQ = t & 15;
    const int rg  = t >> 4;
    #pragma unroll
    for (int si = 0; si < 4; si++) {
        int sp = si * 16 + rg;
        int yy = sp >> 3, xx = sp & 7;
        size_t obase = (size_t)(n * 64 + sp) * K9 + ci0 + ciQ * 4;
        #pragma unroll
        for (int r = 0; r < 9; r++) {
            int y = yy + r / 3 - 1, x = xx + r % 3 - 1;
            uint2 vh = make_uint2(0, 0), vl = make_uint2(0, 0);
            if ((unsigned)y < 8u && (unsigned)x < 8u) {
                int spp = y * 8 + x;
                vh = *(const uint2*)&th[spp][ciQ * 4];
                vl = *(const uint2*)&tl[spp][ciQ * 4];
            }
            *(uint2*)&g_Ah[obase + (size_t)r * 512] = vh;
            *(uint2*)&g_Al[obase + (size_t)r * 512] = vl;
        }
    }
}

// ---------------------------------------------------------------------------
// fp16x3 GEMM conv (R11/R13 mainloop). NEW: smem-staged coalesced epilogues.
//   FIRST, co0<2048 (Q/K): stage packed tile as stg[row][hh*17+ddL]; quads
//     write contiguous 16-dd (64B) runs to g_feats_hl.
//   FIRST, co0>=2048 (V): original scattered path (no contiguous axis).
//   !FIRST: stage f32 tile (stride 133); one thread per (n,co) writes 64
//     contiguous sp floats as 16 float4.
// ---------------------------------------------------------------------------
#define LDK2 20
#define STG_BYTES (4 * 128 * LDK2 * 4)
#define SMEM_BYTES (2 * STG_BYTES)

__device__ __forceinline__ void conv_fill(uint32_t base, int row0, int co0, int k0,
                                          int tid, const __half* gwh, const __half* gwl)
{
    #pragma unroll
    for (int h = 0; h < 2; h++) {
        int c = h * 256 + tid;
        int row = c >> 2, q = c & 3;
        uint32_t doff = (uint32_t)((row * LDK2 + q * 4) * 4);
        size_t aoff = (size_t)(row0 + row) * K9 + k0 + q * 8;
        size_t boff = (size_t)(co0 + row) * K9 + k0 + q * 8;
        cpa16(base + doff,         g_Ah + aoff);
        cpa16(base + 10240 + doff, g_Al + aoff);
        cpa16(base + 20480 + doff, gwh + boff);
        cpa16(base + 30720 + doff, gwl + boff);
    }
    asm volatile("cp.async.commit_group;" ::: "memory");
}

template <int CO, bool FIRST>
__global__ void __launch_bounds__(256, 2)
conv_f16_kernel(const __half* __restrict__ gwh,
                const __half* __restrict__ gwl,
                const float* __restrict__ bias,
                float* __restrict__ out)
{
    extern __shared__ uint32_t sm[];
    const uint32_t smb = (uint32_t)__cvta_generic_to_shared(sm);

    const int row0 = blockIdx.y * 128;
    const int co0  = blockIdx.x * 128;
    const int tid  = threadIdx.x;
    const int lane = tid & 31, wid = tid >> 5;
    const int rbase = (wid >> 1) * 32;
    const int cbase = (wid & 1) * 64;
    const int lg = lane >> 2, lt = lane & 3;

    const int aRow = lane & 15, aCol = (lane >> 4) * 4;
    const int bRow = ((lane >> 4) & 1) * 8 + (lane & 7);
    const int bCol = ((lane >> 3) & 1) * 4;

    float acc[2][8][4] = {};

    conv_fill(smb, row0, co0, 0, tid, gwh, gwl);

    const int NITER = K9 / 32;
    for (int it = 0; it < NITER; it++) {
        const int s = it & 1;
        asm volatile("cp.async.wait_group 0;" ::: "memory");
        __syncthreads();
        if (it + 1 < NITER)
            conv_fill(smb + (1 - s) * STG_BYTES, row0, co0, (it + 1) * 32, tid, gwh, gwl);

        const uint32_t base = smb + s * STG_BYTES;
        #pragma unroll
        for (int k16 = 0; k16 < 2; k16++) {
            const uint32_t ko = k16 * 8;
            uint32_t ah[2][4], al[2][4];
            #pragma unroll
            for (int mt = 0; mt < 2; mt++) {
                uint32_t aw = base + ((rbase + mt * 16 + aRow) * LDK2 + aCol + ko) * 4;
                ldsm4(ah[mt][0], ah[mt][1], ah[mt][2], ah[mt][3], aw);
                ldsm4(al[mt][0], al[mt][1], al[mt][2], al[mt][3], aw + 10240);
            }
            #pragma unroll
            for (int pr = 0; pr < 4; pr++) {
                uint32_t bw = base + 20480 +
                              ((cbase + pr * 16 + bRow) * LDK2 + bCol + ko) * 4;
                uint32_t bh0, bh1, bh2, bh3, bl0, bl1, bl2, bl3;
                ldsm4(bh0, bh1, bh2, bh3, bw);
                ldsm4(bl0, bl1, bl2, bl3, bw + 10240);
                mma_f16(acc[0][2 * pr],     ah[0], bh0, bh1);
                mma_f16(acc[1][2 * pr],     ah[1], bh0, bh1);
                mma_f16(acc[0][2 * pr + 1], ah[0], bh2, bh3);
                mma_f16(acc[1][2 * pr + 1], ah[1], bh2, bh3);
                mma_f16(acc[0][2 * pr],     ah[0], bl0, bl1);
                mma_f16(acc[1][2 * pr],     ah[1], bl0, bl1);
                mma_f16(acc[0][2 * pr + 1], ah[0], bl2, bl3);
                mma_f16(acc[1][2 * pr + 1], ah[1], bl2, bl3);
                mma_f16(acc[0][2 * pr],     al[0], bh0, bh1);
                mma_f16(acc[1][2 * pr],     al[1], bh0, bh1);
                mma_f16(acc[0][2 * pr + 1], al[0], bh2, bh3);
                mma_f16(acc[1][2 * pr + 1], al[1], bh2, bh3);
            }
        }
    }

    // ---- epilogue ----
    if (FIRST && co0 < 2048) {
        // Q/K planes: stage packed tile, then 64B-contiguous dd-runs.
        __syncthreads();                       // all warps done with pipeline smem
        #pragma unroll
        for (int mt = 0; mt < 2; mt++)
            #pragma unroll
            for (int nt = 0; nt < 8; nt++)
                #pragma unroll
                for (int cp = 0; cp < 4; cp++) {
                    int row = rbase + mt * 16 + lg + ((cp >= 2) ? 8 : 0);
                    int col = cbase + nt * 8 + lt * 2 + (cp & 1);
                    float v = acc[mt][nt][cp] + __ldg(&bias[co0 + col]);
                    sm[row * 136 + (col & 7) * 17 + (col >> 3)] = split_h2(v);
                }
        __syncthreads();
        const int e   = co0 >> 9;
        const int dd0 = (co0 & 511) >> 3;
        const int qd = tid >> 2, lt2 = tid & 3;
        #pragma unroll
        for (int it2 = 0; it2 < 16; it2++) {
            int task = it2 * 64 + qd;          // 0..1023 = (row, hh)
            int row = task >> 3, hh = task & 7;
            int grow = row0 + row;
            int n = grow >> 6, sp = grow & 63;
            const uint32_t* src = &sm[row * 136 + hh * 17 + lt2 * 4];
            uint4 v = make_uint4(src[0], src[1], src[2], src[3]);
            size_t o = (((size_t)(e * BP + hh * 64 + sp)) * SEQ + n) * HD + dd0 + lt2 * 4;
            *(uint4*)&g_feats_hl[o] = v;
        }
    } else if (FIRST) {
        // V tiles (e == 4): scattered transpose write (no contiguous axis).
        #pragma unroll
        for (int mt = 0; mt < 2; mt++)
            #pragma unroll
            for (int nt = 0; nt < 8; nt++)
                #pragma unroll
                for (int cp = 0; cp < 4; cp++) {
                    int row = row0 + rbase + mt * 16 + lg + ((cp >= 2) ? 8 : 0);
                    int col = cbase + nt * 8 + lt * 2 + (cp & 1);
                    int co  = co0 + col;
                    float v = acc[mt][nt][cp] + __ldg(&bias[co]);
                    int n = row >> 6, sp = row & 63;
                    int dd = (co >> 3) & 63, hh = co & 7;
                    int bpi = hh * 64 + sp;
                    g_vT[((size_t)bpi * HD + dd) * SEQ + n] = split_h2(v);
                }
    } else {
        // conv_out: stage f32, write 64-sp contiguous runs per (n, co).
        __syncthreads();
        float* stgF = (float*)sm;
        #pragma unroll
        for (int mt = 0; mt < 2; mt++)
            #pragma unroll
            for (int nt = 0; nt < 8; nt++)
                #pragma unroll
                for (int cp = 0; cp < 4; cp++) {
                    int row = rbase + mt * 16 + lg + ((cp >= 2) ? 8 : 0);
                    int col = cbase + nt * 8 + lt * 2 + (cp & 1);
                    stgF[row * 133 + col] = acc[mt][nt][cp] + __ldg(&bias[co0 + col]);
                }
        __syncthreads();
        int n = tid >> 7, co = tid & 127;      // 256 tasks, 1 pass
        int gn = (row0 >> 6) + n;
        size_t obase = ((size_t)gn * CO + co0 + co) * 64;
        #pragma unroll
        for (int q = 0; q < 16; q++) {
            float4 v;
            v.x = stgF[(n * 64 + q * 4 + 0) * 133 + co];
            v.y = stgF[(n * 64 + q * 4 + 1) * 133 + co];
            v.z = stgF[(n * 64 + q * 4 + 2) * 133 + co];
            v.w = stgF[(n * 64 + q * 4 + 3) * 133 + co];
            *(float4*)&out[obase + q * 4] = v;
        }
    }
}

// ---------------------------------------------------------------------------
// Fused QK + dual softmax + agent blend, 32-row q-tiles, 2 CTAs/SM (R13).
// ---------------------------------------------------------------------------
#define FA_SMEM 77312
#define SST 388
#define QH_OFF 12416
#define QL_OFF 13568
#define KH_OFF 14720
#define KL_OFF 17024

__global__ void __launch_bounds__(256, 2)
fused_qk_softmax_kernel(const float* __restrict__ am, const int* __restrict__ agent)
{
    extern __shared__ uint32_t sm[];
    float* Sf = (float*)sm;
    const uint32_t smb = (uint32_t)__cvta_generic_to_shared(sm);

    const int m0 = blockIdx.x * 32;
    const int bp = blockIdx.y;
    const int head = bp >> 6;
    const int tid = threadIdx.x, lane = tid & 31, wid = tid >> 5;
    const int wq   = (wid & 1) * 16;
    const int wcol = (wid >> 1) * 16;
    const int lg = lane >> 2, lt = lane & 3;
    const int aRow = lane & 15, aCol = (lane >> 4) * 4;
    const int bRow = ((lane >> 4) & 1) * 8 + (lane & 7);
    const int bCol = ((lane >> 3) & 1) * 4;

    for (int v = 0; v < 2; v++) {
        const uint32_t* Q = g_feats_hl + (((size_t)(2 + v) * BP + bp) * SEQ + m0) * HD;
        #pragma unroll
        for (int i = 0; i < 2; i++) {
            int lin = i * 256 + tid;
            int row = lin >> 4, q4 = lin & 15;
            uint4 w = *(const uint4*)(Q + (size_t)row * HD + q4 * 4);
            int o = row * 36 + q4 * 2;
            *(uint2*)&sm[QH_OFF + o] = make_uint2(__byte_perm(w.x, w.y, 0x5410),
                                                  __byte_perm(w.z, w.w, 0x5410));
            *(uint2*)&sm[QL_OFF + o] = make_uint2(__byte_perm(w.x, w.y, 0x7632),
                                                  __byte_perm(w.z, w.w, 0x7632));
        }

        const uint32_t* Kv = g_feats_hl + ((size_t)v * BP + bp) * SEQ * HD;
        for (int kc = 0; kc < 6; kc++) {
            __syncthreads();
            #pragma unroll
            for (int i = 0; i < 4; i++) {
                int lin = i * 256 + tid;
                int row = lin >> 4, q4 = lin & 15;
                uint4 w = *(const uint4*)(Kv + (size_t)(kc * 64 + row) * HD + q4 * 4);
                int o = row * 36 + q4 * 2;
                *(uint2*)&sm[KH_OFF + o] = make_uint2(__byte_perm(w.x, w.y, 0x5410),
                                                      __byte_perm(w.z, w.w, 0x5410));
                *(uint2*)&sm[KL_OFF + o] = make_uint2(__byte_perm(w.x, w.y, 0x7632),
                                                      __byte_perm(w.z, w.w, 0x7632));
            }
            __syncthreads();

            float acc[2][4] = {};
            #pragma unroll
            for (int k16 = 0; k16 < 4; k16++) {
                const int ko = k16 * 8;
                uint32_t ah[4], al[4];
                uint32_t aw = smb + (QH_OFF + (wq + aRow) * 36 + aCol + ko) * 4;
                ldsm4(ah[0], ah[1], ah[2], ah[3], aw);
                ldsm4(al[0], al[1], al[2], al[3], aw + (QL_OFF - QH_OFF) * 4);
                uint32_t bw = smb + (KH_OFF + (wcol + bRow) * 36 + bCol + ko) * 4;
                uint32_t bh0, bh1, bh2, bh3, bl0, bl1, bl2, bl3;
                ldsm4(bh0, bh1, bh2, bh3, bw);
                ldsm4(bl0, bl1, bl2, bl3, bw + (KL_OFF - KH_OFF) * 4);
                mma_f16(acc[0], ah, bh0, bh1);
                mma_f16(acc[1], ah, bh2, bh3);
                mma_f16(acc[0], ah, bl0, bl1);
                mma_f16(acc[1], ah, bl2, bl3);
                mma_f16(acc[0], al, bh0, bh1);
                mma_f16(acc[1], al, bh2, bh3);
            }
            #pragma unroll
            for (int nt = 0; nt < 2; nt++) {
                #pragma unroll
                for (int cp = 0; cp < 4; cp++) {
                    int q   = wq + lg + ((cp >= 2) ? 8 : 0);
                    int col = kc * 64 + wcol + nt * 8 + lt * 2 + (cp & 1);
                    Sf[q * SST + col] = acc[nt][cp];
                }
            }
        }
        __syncthreads();

        #pragma unroll
        for (int r4 = 0; r4 < 4; r4++) {
            int row = wid * 4 + r4;
            int gq  = m0 + row;
            const float* amr = am + ((size_t)head * SEQ + gq) * SEQ;
            float e[12];
            float M = -1e30f;
            #pragma unroll
            for (int j = 0; j < 12; j++) {
                float s = Sf[row * SST + lane + 32 * j] * 0.125f + amr[lane + 32 * j];
                e[j] = s;
                M = fmaxf(M, s);
            }
            #pragma unroll
            for (int o = 16; o; o >>= 1) M = fmaxf(M, __shfl_xor_sync(~0u, M, o));
            float Z = 0.f;
            #pragma unroll
            for (int j = 0; j < 12; j++) { e[j] = __expf(e[j] - M); Z += e[j]; }
            #pragma unroll
            for (int o = 16; o; o >>= 1) Z += __shfl_xor_sync(~0u, Z, o);
            float rz = 1.f / Z;

            uint32_t* arow = g_attn + ((size_t)bp * SEQ + gq) * SEQ;
            if (v == 0) {
                #pragma unroll
                for (int j = 0; j < 12; j++)
                    arow[lane + 32 * j] = split_h2(e[j] * rz);
            } else {
                const int* mr = agent + ((size_t)head * SEQ + gq) * SEQ;
                #pragma unroll
                for (int j = 0; j < 12; j++) {
                    float a_same = unsplit_h2(arow[lane + 32 * j]);
                    float m = (float)mr[lane + 32 * j];
                    arow[lane + 32 * j] =
                        split_h2(m * a_same + (1.f - m) * e[j] * rz);
                }
            }
        }
    }
}

// ---------------------------------------------------------------------------
// AV on fp16x3 MMA (unchanged).
// ---------------------------------------------------------------------------
#define AV_SMEM (13824 * 4)

__global__ void __launch_bounds__(256, 2)
av_mma_kernel()
{
    extern __shared__ uint32_t sm[];
    const uint32_t smb = (uint32_t)__cvta_generic_to_shared(sm);

    const int bp = blockIdx.y, m0 = blockIdx.x * 128;
    const int hh = bp >> 6, p = bp & 63;
    const int tid = threadIdx.x, lane = tid & 31, wid = tid >> 5;
    const int rbase = (wid & 3) * 32, cbase = (wid >> 2) * 32;
    const int lg = lane >> 2, lt = lane & 3;
    const int aRow = lane & 15, aCol = (lane >> 4) * 4;
    const int bRow = ((lane >> 4) & 1) * 8 + (lane & 7);
    const int bCol = ((lane >> 3) & 1) * 4;

    const uint32_t* A = g_attn + (size_t)bp * SS2 + (size_t)m0 * SEQ;
    const uint32_t* V = g_vT + (size_t)bp * HD * SEQ;

    float acc[2][4][4] = {};

    for (int ks = 0; ks < 6; ks++) {
        const int k0 = ks * 64;
        __syncthreads();
        #pragma unroll
        for (int i = 0; i < 16; i++) {
            int lin = i * 256 + tid;
            int row = lin >> 5, p2 = lin & 31;
            uint2 w = *(const uint2*)(A + (size_t)row * SEQ + k0 + p2 * 2);
            sm[row * 36 + p2]        = __byte_perm(w.x, w.y, 0x5410);
            sm[4608 + row * 36 + p2] = __byte_perm(w.x, w.y, 0x7632);
        }
        #pragma unroll
        for (int i = 0; i < 8; i++) {
            int lin = i * 256 + tid;
            int row = lin >> 5, p2 = lin & 31;
            uint2 w = *(const uint2*)(V + (size_t)row * SEQ + k0 + p2 * 2);
            sm[9216 + row * 36 + p2]  = __byte_perm(w.x, w.y, 0x5410);
            sm[11520 + row * 36 + p2] = __byte_perm(w.x, w.y, 0x7632);
        }
        __syncthreads();

        #pragma unroll
        for (int k16 = 0; k16 < 4; k16++) {
            const int ko = k16 * 8;
            uint32_t ah[2][4], al[2][4];
            #pragma unroll
            for (int mt = 0; mt < 2; mt++) {
                uint32_t aw = smb + ((rbase + mt * 16 + aRow) * 36 + aCol + ko) * 4;
                ldsm4(ah[mt][0], ah[mt][1], ah[mt][2], ah[mt][3], aw);
                ldsm4(al[mt][0], al[mt][1], al[mt][2], al[mt][3], aw + 18432);
            }
            #pragma unroll
            for (int pr = 0; pr < 2; pr++) {
                uint32_t bw = smb + 36864 + ((cbase + pr * 16 + bRow) * 36 + bCol + ko) * 4;
                uint32_t bh0, bh1, bh2, bh3, bl0, bl1, bl2, bl3;
                ldsm4(bh0, bh1, bh2, bh3, bw);
                ldsm4(bl0, bl1, bl2, bl3, bw + 9216);
                #pragma unroll
                for (int mt = 0; mt < 2; mt++) {
                    mma_f16(acc[mt][2 * pr],     ah[mt], bh0, bh1);
                    mma_f16(acc[mt][2 * pr],     ah[mt], bl0, bl1);
                    mma_f16(acc[mt][2 * pr],     al[mt], bh0, bh1);
                    mma_f16(acc[mt][2 * pr + 1], ah[mt], bh2, bh3);
                    mma_f16(acc[mt][2 * pr + 1], ah[mt], bl2, bl3);
                    mma_f16(acc[mt][2 * pr + 1], al[mt], bh2, bh3);
                }
            }
        }
    }

    #pragma unroll
    for (int mt = 0; mt < 2; mt++) {
        #pragma unroll
        for (int nt = 0; nt < 4; nt++) {
            #pragma unroll
            for (int cp = 0; cp < 4; cp++) {
                int q  = m0 + rbase + mt * 16 + lg + ((cp >= 2) ? 8 : 0);
                int dd = cbase + nt * 8 + lt * 2 + (cp & 1);
                g_c2_hl[((size_t)q * CIN + (dd * 8 + hh)) * 64 + p] =
                    split_h2(acc[mt][nt][cp]);
            }
        }
    }
}

// ---------------------------------------------------------------------------
extern "C" void kernel_launch(void* const* d_in, const int* in_sizes, int n_in,
                              void* d_out, int out_size)
{
    const float* inp       = (const float*)d_in[0];
    const float* attn_mask = (const float*)d_in[1];
    const int*   agent     = (const int*)  d_in[2];
    const float* w_in      = (const float*)d_in[3];
    const float* b_in      = (const float*)d_in[4];
    const float* w_out     = (const float*)d_in[5];
    const float* b_out     = (const float*)d_in[6];
    float*       out       = (float*)d_out;

    __half *wh_in, *wl_in, *wh_out, *wl_out;
    cudaGetSymbolAddress((void**)&wh_in,  g_wh_in);
    cudaGetSymbolAddress((void**)&wl_in,  g_wl_in);
    cudaGetSymbolAddress((void**)&wh_out, g_wh_out);
    cudaGetSymbolAddress((void**)&wl_out, g_wl_out);

    cudaFuncSetAttribute(conv_f16_kernel<2560, true>,
                         cudaFuncAttributeMaxDynamicSharedMemorySize, SMEM_BYTES);
    cudaFuncSetAttribute(conv_f16_kernel<512, false>,
                         cudaFuncAttributeMaxDynamicSharedMemorySize, SMEM_BYTES);
    cudaFuncSetAttribute(fused_qk_softmax_kernel,
                         cudaFuncAttributeMaxDynamicSharedMemorySize, FA_SMEM);
    cudaFuncSetAttribute(av_mma_kernel,
                         cudaFuncAttributeMaxDynamicSharedMemorySize, AV_SMEM);

    const int n_win  = 2560 * K9;
    const int n_wout = 512 * K9;
    split_w_kernel<<<(n_win + 255) / 256, 256>>>(w_in, wh_in, wl_in, n_win);
    split_w_kernel<<<(n_wout + 255) / 256, 256>>>(w_out, wh_out, wl_out, n_wout);

    // im2col expansion of raw input
    im2col_kernel<false><<<dim3(SEQ, 8), 256>>>(inp);

    // conv_in GEMM: M = 24576 (192 blocks of 128), N = 2560 (20 tiles)
    conv_f16_kernel<2560, true><<<dim3(20, 192), 256, SMEM_BYTES>>>(wh_in, wl_in, b_in, nullptr);

    // fused scores + dual softmax + agent blend -> packed attn (32-row tiles)
    fused_qk_softmax_kernel<<<dim3(12, BP), 256, FA_SMEM>>>(attn_mask, agent);

    // attn @ V on tensor cores -> packed conv2 input
    av_mma_kernel<<<dim3(3, BP), 256, AV_SMEM>>>();

    // im2col expansion of attention output (packed source)
    im2col_kernel<true><<<dim3(SEQ, 8), 256>>>(nullptr);

    // conv_out GEMM: N = 512 (4 tiles)
    conv_f16_kernel<512, false><<<dim3(4, 192), 256, SMEM_BYTES>>>(wh_out, wl_out, b_out, out);
}

// round 15
// speedup vs baseline: 1.0398x; 1.0001x over previous
#include <cuda_runtime.h>
#include <cuda_fp16.h>
#include <cstdint>

#define SEQ 384
#define CIN 512
#define HW  64
#define NH  8
#define HD  64
#define K9  (CIN * 9)        // 4608
#define BP  512              // NH * HW batch-pairs
#define NROWS (SEQ * HW)     // 24576 GEMM rows
#define SS2 (SEQ * SEQ)      // 147456

// Scratch (device globals; no runtime allocation)
__device__ uint32_t g_feats_hl[(size_t)4 * BP * SEQ * HD];  // [e][bp][n][dd] packed(hi,lo)
__device__ uint32_t g_vT[(size_t)BP * HD * SEQ];            // [bp][dd][n]   packed(hi,lo)
__device__ uint32_t g_attn[(size_t)BP * SS2];               // v=0 a_same storage, packed
__device__ uint32_t g_c2_hl[(size_t)SEQ * CIN * HW];        // conv2 input, packed(hi,lo)
__device__ __half   g_Ah[(size_t)NROWS * K9];               // im2col hi plane (k' = r*512+ci)
__device__ __half   g_Al[(size_t)NROWS * K9];               // im2col lo plane
__device__ __half   g_wh_in[(size_t)2560 * K9];             // weights hi, k'-order
__device__ __half   g_wl_in[(size_t)2560 * K9];
__device__ __half   g_wh_out[(size_t)512 * K9];
__device__ __half   g_wl_out[(size_t)512 * K9];

// ---------------------------------------------------------------------------
// helpers
// ---------------------------------------------------------------------------
__device__ __forceinline__ uint32_t split_h2(float x)
{
    __half hi = __float2half_rn(x);
    __half lo = __float2half_rn(x - __half2float(hi));
    return (uint32_t)__half_as_ushort(hi) | ((uint32_t)__half_as_ushort(lo) << 16);
}
__device__ __forceinline__ float unsplit_h2(uint32_t p)
{
    return __half2float(__ushort_as_half((unsigned short)(p & 0xFFFF)))
         + __half2float(__ushort_as_half((unsigned short)(p >> 16)));
}

__device__ __forceinline__ void mma_f16(float c[4], const uint32_t a[4],
                                        uint32_t b0, uint32_t b1)
{
    asm volatile(
        "mma.sync.aligned.m16n8k16.row.col.f32.f16.f16.f32 "
        "{%0,%1,%2,%3}, {%4,%5,%6,%7}, {%8,%9}, {%0,%1,%2,%3};"
        : "+f"(c[0]), "+f"(c[1]), "+f"(c[2]), "+f"(c[3])
        : "r"(a[0]), "r"(a[1]), "r"(a[2]), "r"(a[3]), "r"(b0), "r"(b1));
}
__device__ __forceinline__ void ldsm4(uint32_t& r0, uint32_t& r1, uint32_t& r2,
                                      uint32_t& r3, uint32_t addr)
{
    asm volatile("ldmatrix.sync.aligned.m8n8.x4.shared.b16 {%0,%1,%2,%3}, [%4];"
                 : "=r"(r0), "=r"(r1), "=r"(r2), "=r"(r3) : "r"(addr));
}
__device__ __forceinline__ void cpa16(uint32_t dst, const void* src)
{
    asm volatile("cp.async.cg.shared.global [%0], [%1], 16;" :: "r"(dst), "l"(src));
}

// ---------------------------------------------------------------------------
// Weight split + permute to k' = r*512 + ci order
// ---------------------------------------------------------------------------
__global__ void split_w_kernel(const float* __restrict__ w,
                               __half* __restrict__ wh, __half* __restrict__ wl, int n)
{
    int i = blockIdx.x * 256 + threadIdx.x;
    if (i >= n) return;
    int co = i / K9;
    int kn = i - co * K9;
    int r = kn >> 9, ci = kn & 511;
    float x = w[(size_t)co * K9 + ci * 9 + r];
    __half hi = __float2half_rn(x);
    wh[i] = hi;
    wl[i] = __float2half_rn(x - __half2float(hi));
}

// ---------------------------------------------------------------------------
// im2col expansion into hi/lo fp16 planes, k' = r*512 + ci.
// ---------------------------------------------------------------------------
template <bool PACKED>
__global__ __launch_bounds__(256) void im2col_kernel(const float* __restrict__ srcF)
{
    __shared__ ushort th[64][72];
    __shared__ ushort tl[64][72];
    const int n   = blockIdx.x;
    const int ci0 = blockIdx.y * 64;
    const int t   = threadIdx.x;

    {
        int sp4 = (t & 15) * 4;
        int ciL = t >> 4;
        #pragma unroll
        for (int pass = 0; pass < 4; pass++) {
            int ci = pass * 16 + ciL;
            if (PACKED) {
                uint4 w = *(const uint4*)(g_c2_hl + ((size_t)n * CIN + ci0 + ci) * 64 + sp4);
                uint32_t ws[4] = {w.x, w.y, w.z, w.w};
                #pragma unroll
                for (int j = 0; j < 4; j++) {
                    th[sp4 + j][ci] = (ushort)(ws[j] & 0xFFFF);
                    tl[sp4 + j][ci] = (ushort)(ws[j] >> 16);
                }
            } else {
                float4 v = *(const float4*)(srcF + ((size_t)n * CIN + ci0 + ci) * 64 + sp4);
                float vs[4] = {v.x, v.y, v.z, v.w};
                #pragma unroll
                for (int j = 0; j < 4; j++) {
                    __half hi = __float2half_rn(vs[j]);
                    __half lo = __float2half_rn(vs[j] - __half2float(hi));
                    th[sp4 + j][ci] = __half_as_ushort(hi);
                    tl[sp4 + j][ci] = __half_as_ushort(lo);
                }
            }
        }
    }
    __syncthreads();

    const int ciQ = t & 15;
    const int rg  = t >> 4;
    #pragma unroll
    for (int si = 0; si < 4; si++) {
        int sp = si * 16 + rg;
        int yy = sp >> 3, xx = sp & 7;
        size_t obase = (size_t)(n * 64 + sp) * K9 + ci0 + ciQ * 4;
        #pragma unroll
        for (int r = 0; r < 9; r++) {
            int y = yy + r / 3 - 1, x = xx + r % 3 - 1;
            uint2 vh = make_uint2(0, 0), vl = make_uint2(0, 0);
            if ((unsigned)y < 8u && (unsigned)x < 8u) {
                int spp = y * 8 + x;
                vh = *(const uint2*)&th[spp][ciQ * 4];
                vl = *(const uint2*)&tl[spp][ciQ * 4];
            }
            *(uint2*)&g_Ah[obase + (size_t)r * 512] = vh;
            *(uint2*)&g_Al[obase + (size_t)r * 512] = vl;
        }
    }
}

// ---------------------------------------------------------------------------
// fp16x3 GEMM conv (R14 form: proven mainloop + staged coalesced epilogues).
// ---------------------------------------------------------------------------
#define LDK2 20
#define STG_BYTES (4 * 128 * LDK2 * 4)
#define SMEM_BYTES (2 * STG_BYTES)

__device__ __forceinline__ void conv_fill(uint32_t base, int row0, int co0, int k0,
                                          int tid, const __half* gwh, const __half* gwl)
{
    #pragma unroll
    for (int h = 0; h < 2; h++) {
        int c = h * 256 + tid;
        int row = c >> 2, q = c & 3;
        uint32_t doff = (uint32_t)((row * LDK2 + q * 4) * 4);
        size_t aoff = (size_t)(row0 + row) * K9 + k0 + q * 8;
        size_t boff = (size_t)(co0 + row) * K9 + k0 + q * 8;
        cpa16(base + doff,         g_Ah + aoff);
        cpa16(base + 10240 + doff, g_Al + aoff);
        cpa16(base + 20480 + doff, gwh + boff);
        cpa16(base + 30720 + doff, gwl + boff);
    }
    asm volatile("cp.async.commit_group;" ::: "memory");
}

template <int CO, bool FIRST>
__global__ void __launch_bounds__(256, 2)
conv_f16_kernel(const __half* __restrict__ gwh,
                const __half* __restrict__ gwl,
                const float* __restrict__ bias,
                float* __restrict__ out)
{
    extern __shared__ uint32_t sm[];
    const uint32_t smb = (uint32_t)__cvta_generic_to_shared(sm);

    const int row0 = blockIdx.y * 128;
    const int co0  = blockIdx.x * 128;
    const int tid  = threadIdx.x;
    const int lane = tid & 31, wid = tid >> 5;
    const int rbase = (wid >> 1) * 32;
    const int cbase = (wid & 1) * 64;
    const int lg = lane >> 2, lt = lane & 3;

    const int aRow = lane & 15, aCol = (lane >> 4) * 4;
    const int bRow = ((lane >> 4) & 1) * 8 + (lane & 7);
    const int bCol = ((lane >> 3) & 1) * 4;

    float acc[2][8][4] = {};

    conv_fill(smb, row0, co0, 0, tid, gwh, gwl);

    const int NITER = K9 / 32;
    for (int it = 0; it < NITER; it++) {
        const int s = it & 1;
        asm volatile("cp.async.wait_group 0;" ::: "memory");
        __syncthreads();
        if (it + 1 < NITER)
            conv_fill(smb + (1 - s) * STG_BYTES, row0, co0, (it + 1) * 32, tid, gwh, gwl);

        const uint32_t base = smb + s * STG_BYTES;
        #pragma unroll
        for (int k16 = 0; k16 < 2; k16++) {
            const uint32_t ko = k16 * 8;
            uint32_t ah[2][4], al[2][4];
            #pragma unroll
            for (int mt = 0; mt < 2; mt++) {
                uint32_t aw = base + ((rbase + mt * 16 + aRow) * LDK2 + aCol + ko) * 4;
                ldsm4(ah[mt][0], ah[mt][1], ah[mt][2], ah[mt][3], aw);
                ldsm4(al[mt][0], al[mt][1], al[mt][2], al[mt][3], aw + 10240);
            }
            #pragma unroll
            for (int pr = 0; pr < 4; pr++) {
                uint32_t bw = base + 20480 +
                              ((cbase + pr * 16 + bRow) * LDK2 + bCol + ko) * 4;
                uint32_t bh0, bh1, bh2, bh3, bl0, bl1, bl2, bl3;
                ldsm4(bh0, bh1, bh2, bh3, bw);
                ldsm4(bl0, bl1, bl2, bl3, bw + 10240);
                mma_f16(acc[0][2 * pr],     ah[0], bh0, bh1);
                mma_f16(acc[1][2 * pr],     ah[1], bh0, bh1);
                mma_f16(acc[0][2 * pr + 1], ah[0], bh2, bh3);
                mma_f16(acc[1][2 * pr + 1], ah[1], bh2, bh3);
                mma_f16(acc[0][2 * pr],     ah[0], bl0, bl1);
                mma_f16(acc[1][2 * pr],     ah[1], bl0, bl1);
                mma_f16(acc[0][2 * pr + 1], ah[0], bl2, bl3);
                mma_f16(acc[1][2 * pr + 1], ah[1], bl2, bl3);
                mma_f16(acc[0][2 * pr],     al[0], bh0, bh1);
                mma_f16(acc[1][2 * pr],     al[1], bh0, bh1);
                mma_f16(acc[0][2 * pr + 1], al[0], bh2, bh3);
                mma_f16(acc[1][2 * pr + 1], al[1], bh2, bh3);
            }
        }
    }

    // ---- epilogue ----
    if (FIRST && co0 < 2048) {
        __syncthreads();
        #pragma unroll
        for (int mt = 0; mt < 2; mt++)
            #pragma unroll
            for (int nt = 0; nt < 8; nt++)
                #pragma unroll
                for (int cp = 0; cp < 4; cp++) {
                    int row = rbase + mt * 16 + lg + ((cp >= 2) ? 8 : 0);
                    int col = cbase + nt * 8 + lt * 2 + (cp & 1);
                    float v = acc[mt][nt][cp] + __ldg(&bias[co0 + col]);
                    sm[row * 136 + (col & 7) * 17 + (col >> 3)] = split_h2(v);
                }
        __syncthreads();
        const int e   = co0 >> 9;
        const int dd0 = (co0 & 511) >> 3;
        const int qd = tid >> 2, lt2 = tid & 3;
        #pragma unroll
        for (int it2 = 0; it2 < 16; it2++) {
            int task = it2 * 64 + qd;
            int row = task >> 3, hh = task & 7;
            int grow = row0 + row;
            int n = grow >> 6, sp = grow & 63;
            const uint32_t* src = &sm[row * 136 + hh * 17 + lt2 * 4];
            uint4 v = make_uint4(src[0], src[1], src[2], src[3]);
            size_t o = (((size_t)(e * BP + hh * 64 + sp)) * SEQ + n) * HD + dd0 + lt2 * 4;
            *(uint4*)&g_feats_hl[o] = v;
        }
    } else if (FIRST) {
        #pragma unroll
        for (int mt = 0; mt < 2; mt++)
            #pragma unroll
            for (int nt = 0; nt < 8; nt++)
                #pragma unroll
                for (int cp = 0; cp < 4; cp++) {
                    int row = row0 + rbase + mt * 16 + lg + ((cp >= 2) ? 8 : 0);
                    int col = cbase + nt * 8 + lt * 2 + (cp & 1);
                    int co  = co0 + col;
                    float v = acc[mt][nt][cp] + __ldg(&bias[co]);
                    int n = row >> 6, sp = row & 63;
                    int dd = (co >> 3) & 63, hh = co & 7;
                    int bpi = hh * 64 + sp;
                    g_vT[((size_t)bpi * HD + dd) * SEQ + n] = split_h2(v);
                }
    } else {
        __syncthreads();
        float* stgF = (float*)sm;
        #pragma unroll
        for (int mt = 0; mt < 2; mt++)
            #pragma unroll
            for (int nt = 0; nt < 8; nt++)
                #pragma unroll
                for (int cp = 0; cp < 4; cp++) {
                    int row = rbase + mt * 16 + lg + ((cp >= 2) ? 8 : 0);
                    int col = cbase + nt * 8 + lt * 2 + (cp & 1);
                    stgF[row * 133 + col] = acc[mt][nt][cp] + __ldg(&bias[co0 + col]);
                }
        __syncthreads();
        int n = tid >> 7, co = tid & 127;
        int gn = (row0 >> 6) + n;
        size_t obase = ((size_t)gn * CO + co0 + co) * 64;
        #pragma unroll
        for (int q = 0; q < 16; q++) {
            float4 v;
            v.x = stgF[(n * 64 + q * 4 + 0) * 133 + co];
            v.y = stgF[(n * 64 + q * 4 + 1) * 133 + co];
            v.z = stgF[(n * 64 + q * 4 + 2) * 133 + co];
            v.w = stgF[(n * 64 + q * 4 + 3) * 133 + co];
            *(float4*)&out[obase + q * 4] = v;
        }
    }
}

// ---------------------------------------------------------------------------
// Fused QK + dual softmax + agent blend + AV. 32-row q-tiles, 2 CTAs/SM.
// QK/softmax as R13. v=1 blend writes packed attn IN PLACE into Sf; then AV:
// 6 chunks of k=64, A-planes built from packed Sf into QH/QL (1152 w each),
// V-planes into KH/KL (2304 w each). Output O[32x64] scattered to g_c2_hl.
// ---------------------------------------------------------------------------
#define FA_SMEM 77312
#define SST 388
#define QH_OFF 12416
#define QL_OFF 13568
#define KH_OFF 14720
#define KL_OFF 17024

__global__ void __launch_bounds__(256, 2)
fused_attn_kernel(const float* __restrict__ am, const int* __restrict__ agent)
{
    extern __shared__ uint32_t sm[];
    float* Sf = (float*)sm;
    const uint32_t smb = (uint32_t)__cvta_generic_to_shared(sm);

    const int m0 = blockIdx.x * 32;
    const int bp = blockIdx.y;
    const int head = bp >> 6;
    const int tid = threadIdx.x, lane = tid & 31, wid = tid >> 5;
    const int wq   = (wid & 1) * 16;
    const int wcol = (wid >> 1) * 16;
    const int lg = lane >> 2, lt = lane & 3;
    const int aRow = lane & 15, aCol = (lane >> 4) * 4;
    const int bRow = ((lane >> 4) & 1) * 8 + (lane & 7);
    const int bCol = ((lane >> 3) & 1) * 4;

    for (int v = 0; v < 2; v++) {
        const uint32_t* Q = g_feats_hl + (((size_t)(2 + v) * BP + bp) * SEQ + m0) * HD;
        #pragma unroll
        for (int i = 0; i < 2; i++) {
            int lin = i * 256 + tid;
            int row = lin >> 4, q4 = lin & 15;
            uint4 w = *(const uint4*)(Q + (size_t)row * HD + q4 * 4);
            int o = row * 36 + q4 * 2;
            *(uint2*)&sm[QH_OFF + o] = make_uint2(__byte_perm(w.x, w.y, 0x5410),
                                                  __byte_perm(w.z, w.w, 0x5410));
            *(uint2*)&sm[QL_OFF + o] = make_uint2(__byte_perm(w.x, w.y, 0x7632),
                                                  __byte_perm(w.z, w.w, 0x7632));
        }

        const uint32_t* Kv = g_feats_hl + ((size_t)v * BP + bp) * SEQ * HD;
        for (int kc = 0; kc < 6; kc++) {
            __syncthreads();
            #pragma unroll
            for (int i = 0; i < 4; i++) {
                int lin = i * 256 + tid;
                int row = lin >> 4, q4 = lin & 15;
                uint4 w = *(const uint4*)(Kv + (size_t)(kc * 64 + row) * HD + q4 * 4);
                int o = row * 36 + q4 * 2;
                *(uint2*)&sm[KH_OFF + o] = make_uint2(__byte_perm(w.x, w.y, 0x5410),
                                                      __byte_perm(w.z, w.w, 0x5410));
                *(uint2*)&sm[KL_OFF + o] = make_uint2(__byte_perm(w.x, w.y, 0x7632),
                                                      __byte_perm(w.z, w.w, 0x7632));
            }
            __syncthreads();

            float acc[2][4] = {};
            #pragma unroll
            for (int k16 = 0; k16 < 4; k16++) {
                const int ko = k16 * 8;
                uint32_t ah[4], al[4];
                uint32_t aw = smb + (QH_OFF + (wq + aRow) * 36 + aCol + ko) * 4;
                ldsm4(ah[0], ah[1], ah[2], ah[3], aw);
                ldsm4(al[0], al[1], al[2], al[3], aw + (QL_OFF - QH_OFF) * 4);
                uint32_t bw = smb + (KH_OFF + (wcol + bRow) * 36 + bCol + ko) * 4;
                uint32_t bh0, bh1, bh2, bh3, bl0, bl1, bl2, bl3;
                ldsm4(bh0, bh1, bh2, bh3, bw);
                ldsm4(bl0, bl1, bl2, bl3, bw + (KL_OFF - KH_OFF) * 4);
                mma_f16(acc[0], ah, bh0, bh1);
                mma_f16(acc[1], ah, bh2, bh3);
                mma_f16(acc[0], ah, bl0, bl1);
                mma_f16(acc[1], ah, bl2, bl3);
                mma_f16(acc[0], al, bh0, bh1);
                mma_f16(acc[1], al, bh2, bh3);
            }
            #pragma unroll
            for (int nt = 0; nt < 2; nt++) {
                #pragma unroll
                for (int cp = 0; cp < 4; cp++) {
                    int q   = wq + lg + ((cp >= 2) ? 8 : 0);
                    int col = kc * 64 + wcol + nt * 8 + lt * 2 + (cp & 1);
                    Sf[q * SST + col] = acc[nt][cp];
                }
            }
        }
        __syncthreads();

        #pragma unroll
        for (int r4 = 0; r4 < 4; r4++) {
            int row = wid * 4 + r4;
            int gq  = m0 + row;
            const float* amr = am + ((size_t)head * SEQ + gq) * SEQ;
            float e[12];
            float M = -1e30f;
            #pragma unroll
            for (int j = 0; j < 12; j++) {
                float s = Sf[row * SST + lane + 32 * j] * 0.125f + amr[lane + 32 * j];
                e[j] = s;
                M = fmaxf(M, s);
            }
            #pragma unroll
            for (int o = 16; o; o >>= 1) M = fmaxf(M, __shfl_xor_sync(~0u, M, o));
            float Z = 0.f;
            #pragma unroll
            for (int j = 0; j < 12; j++) { e[j] = __expf(e[j] - M); Z += e[j]; }
            #pragma unroll
            for (int o = 16; o; o >>= 1) Z += __shfl_xor_sync(~0u, Z, o);
            float rz = 1.f / Z;

            uint32_t* arow = g_attn + ((size_t)bp * SEQ + gq) * SEQ;
            if (v == 0) {
                // store a_same packed for the v=1 blend
                #pragma unroll
                for (int j = 0; j < 12; j++)
                    arow[lane + 32 * j] = split_h2(e[j] * rz);
            } else {
                // blend and write packed attn IN PLACE into Sf (same word this
                // thread just read -> no cross-thread hazard)
                const int* mr = agent + ((size_t)head * SEQ + gq) * SEQ;
                #pragma unroll
                for (int j = 0; j < 12; j++) {
                    float a_same = unsplit_h2(arow[lane + 32 * j]);
                    float m = (float)mr[lane + 32 * j];
                    ((uint32_t*)Sf)[row * SST + lane + 32 * j] =
                        split_h2(m * a_same + (1.f - m) * e[j] * rz);
                }
            }
        }
    }

    // ---- AV phase: O[32 x 64] = attn(Sf packed) @ V, 6 chunks of k=64 ----
    const uint32_t* SfU = sm;   // packed attn, rows stride SST
    const uint32_t* Vp  = g_vT + (size_t)bp * HD * SEQ;
    const int hh2 = bp >> 6, p = bp & 63;

    float accv[2][4] = {};
    for (int kc = 0; kc < 6; kc++) {
        __syncthreads();   // kc=0: blend writes done; kc>0: prev MMA reads done
        // A-chunk planes (32 rows x 32 words) into QH/QL
        #pragma unroll
        for (int i = 0; i < 4; i++) {
            int task = i * 256 + tid;
            int row = task >> 5, w = task & 31;
            uint32_t p0 = SfU[row * SST + kc * 64 + 2 * w];
            uint32_t p1 = SfU[row * SST + kc * 64 + 2 * w + 1];
            sm[QH_OFF + row * 36 + w] = __byte_perm(p0, p1, 0x5410);
            sm[QL_OFF + row * 36 + w] = __byte_perm(p0, p1, 0x7632);
        }
        // V-chunk planes (64 dd x 32 words) into KH/KL
        #pragma unroll
        for (int i = 0; i < 8; i++) {
            int task = i * 256 + tid;
            int dd = task >> 5, w = task & 31;
            uint2 wv = *(const uint2*)(Vp + (size_t)dd * SEQ + kc * 64 + 2 * w);
            sm[KH_OFF + dd * 36 + w] = __byte_perm(wv.x, wv.y, 0x5410);
            sm[KL_OFF + dd * 36 + w] = __byte_perm(wv.x, wv.y, 0x7632);
        }
        __syncthreads();

        #pragma unroll
        for (int k16 = 0; k16 < 4; k16++) {
            const int ko = k16 * 8;
            uint32_t ah[4], al[4];
            uint32_t aw = smb + (QH_OFF + (wq + aRow) * 36 + aCol + ko) * 4;
            ldsm4(ah[0], ah[1], ah[2], ah[3], aw);
            ldsm4(al[0], al[1], al[2], al[3], aw + (QL_OFF - QH_OFF) * 4);
            uint32_t bw = smb + (KH_OFF + (wcol + bRow) * 36 + bCol + ko) * 4;
            uint32_t bh0, bh1, bh2, bh3, bl0, bl1, bl2, bl3;
            ldsm4(bh0, bh1, bh2, bh3, bw);
            ldsm4(bl0, bl1, bl2, bl3, bw + (KL_OFF - KH_OFF) * 4);
            mma_f16(accv[0], ah, bh0, bh1);
            mma_f16(accv[0], ah, bl0, bl1);
            mma_f16(accv[0], al, bh0, bh1);
            mma_f16(accv[1], ah, bh2, bh3);
            mma_f16(accv[1], ah, bl2, bl3);
            mma_f16(accv[1], al, bh2, bh3);
        }
    }

    #pragma unroll
    for (int nt = 0; nt < 2; nt++) {
        #pragma unroll
        for (int cp = 0; cp < 4; cp++) {
            int q  = m0 + wq + lg + ((cp >= 2) ? 8 : 0);
            int dd = wcol + nt * 8 + lt * 2 + (cp & 1);
            g_c2_hl[((size_t)q * CIN + (dd * 8 + hh2)) * 64 + p] =
                split_h2(accv[nt][cp]);
        }
    }
}

// ---------------------------------------------------------------------------
extern "C" void kernel_launch(void* const* d_in, const int* in_sizes, int n_in,
                              void* d_out, int out_size)
{
    const float* inp       = (const float*)d_in[0];
    const float* attn_mask = (const float*)d_in[1];
    const int*   agent     = (const int*)  d_in[2];
    const float* w_in      = (const float*)d_in[3];
    const float* b_in      = (const float*)d_in[4];
    const float* w_out     = (const float*)d_in[5];
    const float* b_out     = (const float*)d_in[6];
    float*       out       = (float*)d_out;

    __half *wh_in, *wl_in, *wh_out, *wl_out;
    cudaGetSymbolAddress((void**)&wh_in,  g_wh_in);
    cudaGetSymbolAddress((void**)&wl_in,  g_wl_in);
    cudaGetSymbolAddress((void**)&wh_out, g_wh_out);
    cudaGetSymbolAddress((void**)&wl_out, g_wl_out);

    cudaFuncSetAttribute(conv_f16_kernel<2560, true>,
                         cudaFuncAttributeMaxDynamicSharedMemorySize, SMEM_BYTES);
    cudaFuncSetAttribute(conv_f16_kernel<512, false>,
                         cudaFuncAttributeMaxDynamicSharedMemorySize, SMEM_BYTES);
    cudaFuncSetAttribute(fused_attn_kernel,
                         cudaFuncAttributeMaxDynamicSharedMemorySize, FA_SMEM);

    const int n_win  = 2560 * K9;
    const int n_wout = 512 * K9;
    split_w_kernel<<<(n_win + 255) / 256, 256>>>(w_in, wh_in, wl_in, n_win);
    split_w_kernel<<<(n_wout + 255) / 256, 256>>>(w_out, wh_out, wl_out, n_wout);

    // im2col expansion of raw input
    im2col_kernel<false><<<dim3(SEQ, 8), 256>>>(inp);

    // conv_in GEMM: M = 24576 (192 blocks of 128), N = 2560 (20 tiles)
    conv_f16_kernel<2560, true><<<dim3(20, 192), 256, SMEM_BYTES>>>(wh_in, wl_in, b_in, nullptr);

    // fused scores + dual softmax + agent blend + AV -> packed conv2 input
    fused_attn_kernel<<<dim3(12, BP), 256, FA_SMEM>>>(attn_mask, agent);

    // im2col expansion of attention output (packed source)
    im2col_kernel<true><<<dim3(SEQ, 8), 256>>>(nullptr);

    // conv_out GEMM: N = 512 (4 tiles)
    conv_f16_kernel<512, false><<<dim3(4, 192), 256, SMEM_BYTES>>>(wh_out, wl_out, b_out, out);
}